// round 3
// baseline (speedup 1.0000x reference)
#include <cuda_runtime.h>
#include <math_constants.h>

#define NN 500000
#define DD 256
#define CC 128
#define SS 2048

// Scratch for hidden activations h = relu(H@W1+b1): 500000*256 fp32 = 512 MB.
__device__ float g_h[(long long)NN * DD];

// ---------------------------------------------------------------------------
// Tiled fp32 GEMM:  Cout[M,N] = act(A[M,256] @ B[256,N] + bias)
// BM=128, BN=128, BK=16, 256 threads, 8x8 per-thread microtile.
// ---------------------------------------------------------------------------
__global__ __launch_bounds__(256) void sgemm_k256(
    const float* __restrict__ A, const float* __restrict__ B,
    const float* __restrict__ bias, float* __restrict__ Cout,
    int M, int N, int relu)
{
    __shared__ float As[16][128];   // [k][m]
    __shared__ float Bs[16][128];   // [k][n]

    const int tid  = threadIdx.x;
    const int m0   = blockIdx.x * 128;
    const int n0   = blockIdx.y * 128;
    const int trow = tid >> 4;      // 0..15
    const int tcol = tid & 15;      // 0..15

    float acc[8][8];
#pragma unroll
    for (int i = 0; i < 8; i++)
#pragma unroll
        for (int j = 0; j < 8; j++) acc[i][j] = 0.f;

    for (int k0 = 0; k0 < DD; k0 += 16) {
#pragma unroll
        for (int l = 0; l < 2; l++) {
            int idx = tid + 256 * l;
            int r   = idx >> 2;        // 0..127
            int c4  = idx & 3;         // 0..3
            int grow = m0 + r;
            float4 v = make_float4(0.f, 0.f, 0.f, 0.f);
            if (grow < M)
                v = *reinterpret_cast<const float4*>(&A[(size_t)grow * DD + k0 + c4 * 4]);
            As[c4 * 4 + 0][r] = v.x;
            As[c4 * 4 + 1][r] = v.y;
            As[c4 * 4 + 2][r] = v.z;
            As[c4 * 4 + 3][r] = v.w;
        }
#pragma unroll
        for (int l = 0; l < 2; l++) {
            int idx = tid + 256 * l;
            int r   = idx >> 5;        // 0..15
            int c4  = idx & 31;        // 0..31
            float4 v = *reinterpret_cast<const float4*>(
                &B[(size_t)(k0 + r) * N + n0 + c4 * 4]);
            *reinterpret_cast<float4*>(&Bs[r][c4 * 4]) = v;
        }
        __syncthreads();

#pragma unroll
        for (int k = 0; k < 16; k++) {
            float a[8], b[8];
#pragma unroll
            for (int i = 0; i < 8; i++) a[i] = As[k][trow * 8 + i];
#pragma unroll
            for (int j = 0; j < 8; j++) b[j] = Bs[k][tcol * 8 + j];
#pragma unroll
            for (int i = 0; i < 8; i++)
#pragma unroll
                for (int j = 0; j < 8; j++)
                    acc[i][j] = fmaf(a[i], b[j], acc[i][j]);
        }
        __syncthreads();
    }

#pragma unroll
    for (int i = 0; i < 8; i++) {
        int grow = m0 + trow * 8 + i;
        if (grow < M) {
#pragma unroll
            for (int j4 = 0; j4 < 2; j4++) {
                int gc = n0 + tcol * 8 + j4 * 4;
                float4 bb = *reinterpret_cast<const float4*>(&bias[gc]);
                float4 o;
                o.x = acc[i][j4 * 4 + 0] + bb.x;
                o.y = acc[i][j4 * 4 + 1] + bb.y;
                o.z = acc[i][j4 * 4 + 2] + bb.z;
                o.w = acc[i][j4 * 4 + 3] + bb.w;
                if (relu) {
                    o.x = fmaxf(o.x, 0.f);
                    o.y = fmaxf(o.y, 0.f);
                    o.z = fmaxf(o.z, 0.f);
                    o.w = fmaxf(o.w, 0.f);
                }
                *reinterpret_cast<float4*>(&Cout[(size_t)grow * N + gc]) = o;
            }
        }
    }
}

// ---------------------------------------------------------------------------
// Segment softmax over sorted int32 segment ids.
// One block per segment, 128 threads = one per class column.
// ---------------------------------------------------------------------------
__device__ __forceinline__ int lower_bound_i32(const int* __restrict__ a,
                                               int n, int key)
{
    int lo = 0, hi = n;
    while (lo < hi) {
        int mid = (lo + hi) >> 1;
        if (a[mid] < key) lo = mid + 1; else hi = mid;
    }
    return lo;
}

__global__ __launch_bounds__(128) void seg_softmax(
    const float* __restrict__ logits,
    const int* __restrict__ batch,
    float* __restrict__ probs)
{
    const int s  = blockIdx.x;
    const int lo = lower_bound_i32(batch, NN, s);
    const int hi = lower_bound_i32(batch, NN, s + 1);
    const int c  = threadIdx.x;

    if (lo >= hi) return;   // empty segment

    float m = -CUDART_INF_F;
    for (int r = lo; r < hi; r++)
        m = fmaxf(m, logits[(size_t)r * CC + c]);

    float sum = 0.f;
    for (int r = lo; r < hi; r++)
        sum += __expf(logits[(size_t)r * CC + c] - m);

    float inv = 1.f / sum;
    for (int r = lo; r < hi; r++)
        probs[(size_t)r * CC + c] = __expf(logits[(size_t)r * CC + c] - m) * inv;
}

// ---------------------------------------------------------------------------
// Launch
// ---------------------------------------------------------------------------
extern "C" void kernel_launch(void* const* d_in, const int* in_sizes, int n_in,
                              void* d_out, int out_size)
{
    const float* H  = nullptr;
    const int*   batch = nullptr;
    const float* W1 = nullptr;
    const float* b1 = nullptr;
    const float* W2 = nullptr;
    const float* b2 = nullptr;

    for (int i = 0; i < n_in; i++) {
        switch (in_sizes[i]) {
            case 128000000: H     = (const float*)d_in[i]; break;
            case 500000:    batch = (const int*)d_in[i];   break;
            case 65536:     W1    = (const float*)d_in[i]; break;
            case 256:       b1    = (const float*)d_in[i]; break;
            case 32768:     W2    = (const float*)d_in[i]; break;
            case 128:       b2    = (const float*)d_in[i]; break;
            default: break; // num_segments scalar etc.
        }
    }

    float* out    = (float*)d_out;
    float* logits = out;                       // [NN, CC]
    float* probs  = out + (size_t)NN * CC;     // [NN, CC]

    void* h_sym = nullptr;
    cudaGetSymbolAddress(&h_sym, g_h);
    float* hbuf = (float*)h_sym;

    const int mblocks = (NN + 127) / 128;      // 3907

    dim3 g1(mblocks, DD / 128);
    sgemm_k256<<<g1, 256>>>(H, W1, b1, hbuf, NN, DD, 1);

    dim3 g2(mblocks, CC / 128);
    sgemm_k256<<<g2, 256>>>(hbuf, W2, b2, logits, NN, CC, 0);

    seg_softmax<<<SS, 128>>>(logits, batch, probs);
}

// round 5
// speedup vs baseline: 1.3919x; 1.3919x over previous
#include <cuda_runtime.h>
#include <cuda_bf16.h>
#include <math_constants.h>
#include <cstdint>

#define NN 500000
#define DD 256
#define CC 128
#define SSEG 2048

#define BM 128
#define BN 64
#define BK 32
#define APITCH 136   // words per kk-row of A (128 m + 8 pad)
#define BPITCH 72    // words per kk-row of B (64 n + 8 pad)

// Scratch for hidden activations h = relu(H@W1+b1): 500000*256 fp32 = 512 MB.
__device__ float g_h[(long long)NN * DD];

#define MMA16816(d, a, b)                                                     \
    asm volatile(                                                             \
        "mma.sync.aligned.m16n8k16.row.col.f32.bf16.bf16.f32 "                \
        "{%0,%1,%2,%3}, {%4,%5,%6,%7}, {%8,%9}, {%0,%1,%2,%3};"               \
        : "+f"((d)[0]), "+f"((d)[1]), "+f"((d)[2]), "+f"((d)[3])              \
        : "r"((a)[0]), "r"((a)[1]), "r"((a)[2]), "r"((a)[3]),                 \
          "r"((b)[0]), "r"((b)[1]))

// pack two floats as bf16x2 (lo in low 16 bits), plus their residuals.
__device__ __forceinline__ uint32_t pack_hi(float x, float y) {
    __nv_bfloat162 h = __floats2bfloat162_rn(x, y);
    return *reinterpret_cast<uint32_t*>(&h);
}
__device__ __forceinline__ uint32_t pack_lo(float x, float y) {
    __nv_bfloat162 h = __floats2bfloat162_rn(x, y);
    float rx = x - __low2float(h);
    float ry = y - __high2float(h);
    __nv_bfloat162 l = __floats2bfloat162_rn(rx, ry);
    return *reinterpret_cast<uint32_t*>(&l);
}

// ===========================================================================
// HMMA bf16-split GEMM: Cout[M,Nfull] = act(A[M,256] @ W[256,Nfull] + bias)
// CTA 128x64, 8 warps (4m x 2n), warp tile 32x32, K chunks of 32.
// 3 products: Ah*Bh + Ah*Bl + Al*Bh  (split-precision, err ~2^-16)
// ===========================================================================
__global__ __launch_bounds__(256, 2)
void gemm_hmma(const float* __restrict__ A, const float* __restrict__ W,
               const float* __restrict__ bias, float* __restrict__ Cout,
               int M, int Nfull, int relu)
{
    __shared__ uint32_t sAhi[16 * APITCH];
    __shared__ uint32_t sAlo[16 * APITCH];
    __shared__ uint32_t sBhi[16 * BPITCH];
    __shared__ uint32_t sBlo[16 * BPITCH];
    __shared__ float    sbias[BN];

    const int tid  = threadIdx.x;
    const int lane = tid & 31;
    const int wid  = tid >> 5;
    const int wm   = wid & 3;        // 0..3  -> m offset wm*32
    const int wn   = wid >> 2;       // 0..1  -> n offset wn*32
    const int gid  = lane >> 2;      // 0..7
    const int tig  = lane & 3;       // 0..3
    const int m0   = blockIdx.x * BM;
    const int n0   = blockIdx.y * BN;

    if (tid < BN) sbias[tid] = bias[n0 + tid];

    float acc[2][4][4];
#pragma unroll
    for (int mt = 0; mt < 2; mt++)
#pragma unroll
        for (int nt = 0; nt < 4; nt++)
#pragma unroll
            for (int i = 0; i < 4; i++) acc[mt][nt][i] = 0.f;

    // Prefetch register staging
    // A: 128x32 floats = 1024 float4 / 256 thr = 4 each.
    //    f4 = tid + 256*l : m = tid & 127, kq = (tid>>7) + 2*l
    // B: kk = tid>>4 (0..15), n4 = tid&15 ; reads rows k0+2kk and k0+2kk+1.
    const int am  = tid & 127;
    const int akq = tid >> 7;
    const int bkk = tid >> 4;
    const int bn4 = tid & 15;

    float4 ra[4], rb0, rb1;

    // ---- prefetch chunk 0 ----
    {
        const int k0 = 0;
#pragma unroll
        for (int l = 0; l < 4; l++) {
            int kq = akq + 2 * l;
            int grow = m0 + am;
            ra[l] = (grow < M)
                ? *reinterpret_cast<const float4*>(&A[(size_t)grow * DD + k0 + kq * 4])
                : make_float4(0.f, 0.f, 0.f, 0.f);
        }
        rb0 = *reinterpret_cast<const float4*>(&W[(size_t)(k0 + 2 * bkk)     * Nfull + n0 + bn4 * 4]);
        rb1 = *reinterpret_cast<const float4*>(&W[(size_t)(k0 + 2 * bkk + 1) * Nfull + n0 + bn4 * 4]);
    }

#pragma unroll 1
    for (int c = 0; c < 8; c++) {
        __syncthreads();   // previous compute done (and sbias ready on c==0)

        // ---- convert + store to SMEM ----
#pragma unroll
        for (int l = 0; l < 4; l++) {
            int kq = akq + 2 * l;
            float4 v = ra[l];
            sAhi[(2 * kq    ) * APITCH + am] = pack_hi(v.x, v.y);
            sAlo[(2 * kq    ) * APITCH + am] = pack_lo(v.x, v.y);
            sAhi[(2 * kq + 1) * APITCH + am] = pack_hi(v.z, v.w);
            sAlo[(2 * kq + 1) * APITCH + am] = pack_lo(v.z, v.w);
        }
        {
            uint32_t ph[4], pl[4];
            ph[0] = pack_hi(rb0.x, rb1.x);  pl[0] = pack_lo(rb0.x, rb1.x);
            ph[1] = pack_hi(rb0.y, rb1.y);  pl[1] = pack_lo(rb0.y, rb1.y);
            ph[2] = pack_hi(rb0.z, rb1.z);  pl[2] = pack_lo(rb0.z, rb1.z);
            ph[3] = pack_hi(rb0.w, rb1.w);  pl[3] = pack_lo(rb0.w, rb1.w);
            *reinterpret_cast<uint4*>(&sBhi[bkk * BPITCH + bn4 * 4]) =
                make_uint4(ph[0], ph[1], ph[2], ph[3]);
            *reinterpret_cast<uint4*>(&sBlo[bkk * BPITCH + bn4 * 4]) =
                make_uint4(pl[0], pl[1], pl[2], pl[3]);
        }
        __syncthreads();

        // ---- prefetch next chunk (in flight during compute) ----
        if (c < 7) {
            const int k0 = (c + 1) * BK;
#pragma unroll
            for (int l = 0; l < 4; l++) {
                int kq = akq + 2 * l;
                int grow = m0 + am;
                ra[l] = (grow < M)
                    ? *reinterpret_cast<const float4*>(&A[(size_t)grow * DD + k0 + kq * 4])
                    : make_float4(0.f, 0.f, 0.f, 0.f);
            }
            rb0 = *reinterpret_cast<const float4*>(&W[(size_t)(k0 + 2 * bkk)     * Nfull + n0 + bn4 * 4]);
            rb1 = *reinterpret_cast<const float4*>(&W[(size_t)(k0 + 2 * bkk + 1) * Nfull + n0 + bn4 * 4]);
        }

        // ---- compute: 3 products x 2 k16-steps ----
#pragma unroll
        for (int p = 0; p < 3; p++) {
            const uint32_t* sa = (p < 2)  ? sAhi : sAlo;
            const uint32_t* sb = (p == 1) ? sBlo : sBhi;
#pragma unroll
            for (int s = 0; s < 2; s++) {
                const int kk = s * 8 + tig;
                uint32_t af[2][4], bfr[4][2];
#pragma unroll
                for (int mt = 0; mt < 2; mt++) {
                    int mrow = wm * 32 + mt * 16 + gid;
                    af[mt][0] = sa[(kk    ) * APITCH + mrow];
                    af[mt][1] = sa[(kk    ) * APITCH + mrow + 8];
                    af[mt][2] = sa[(kk + 4) * APITCH + mrow];
                    af[mt][3] = sa[(kk + 4) * APITCH + mrow + 8];
                }
#pragma unroll
                for (int nt = 0; nt < 4; nt++) {
                    int ncol = wn * 32 + nt * 8 + gid;
                    bfr[nt][0] = sb[(kk    ) * BPITCH + ncol];
                    bfr[nt][1] = sb[(kk + 4) * BPITCH + ncol];
                }
#pragma unroll
                for (int mt = 0; mt < 2; mt++)
#pragma unroll
                    for (int nt = 0; nt < 4; nt++)
                        MMA16816(acc[mt][nt], af[mt], bfr[nt]);
            }
        }
    }

    // ---- epilogue: bias (+ReLU), float2 stores ----
#pragma unroll
    for (int mt = 0; mt < 2; mt++) {
        int r0 = m0 + wm * 32 + mt * 16 + gid;
#pragma unroll
        for (int nt = 0; nt < 4; nt++) {
            int col = wn * 32 + nt * 8 + 2 * tig;
            float bv0 = sbias[col], bv1 = sbias[col + 1];
            float x0 = acc[mt][nt][0] + bv0;
            float x1 = acc[mt][nt][1] + bv1;
            float x2 = acc[mt][nt][2] + bv0;
            float x3 = acc[mt][nt][3] + bv1;
            if (relu) {
                x0 = fmaxf(x0, 0.f); x1 = fmaxf(x1, 0.f);
                x2 = fmaxf(x2, 0.f); x3 = fmaxf(x3, 0.f);
            }
            if (r0 < M) {
                float2 o = make_float2(x0, x1);
                *reinterpret_cast<float2*>(&Cout[(size_t)r0 * Nfull + n0 + col]) = o;
            }
            if (r0 + 8 < M) {
                float2 o = make_float2(x2, x3);
                *reinterpret_cast<float2*>(&Cout[(size_t)(r0 + 8) * Nfull + n0 + col]) = o;
            }
        }
    }
}

// ===========================================================================
// Segment softmax, online 2-pass. One block/segment, thread = class column.
// ===========================================================================
__device__ __forceinline__ int lower_bound_i32(const int* __restrict__ a,
                                               int n, int key)
{
    int lo = 0, hi = n;
    while (lo < hi) {
        int mid = (lo + hi) >> 1;
        if (a[mid] < key) lo = mid + 1; else hi = mid;
    }
    return lo;
}

__global__ __launch_bounds__(128) void seg_softmax(
    const float* __restrict__ logits,
    const int* __restrict__ batch,
    float* __restrict__ probs)
{
    const int s  = blockIdx.x;
    const int lo = lower_bound_i32(batch, NN, s);
    const int hi = lower_bound_i32(batch, NN, s + 1);
    const int c  = threadIdx.x;
    if (lo >= hi) return;

    float m = -CUDART_INF_F, sum = 0.f;
    for (int r = lo; r < hi; r++) {
        float x = logits[(size_t)r * CC + c];
        if (x > m) {
            sum = sum * __expf(m - x) + 1.f;
            m = x;
        } else {
            sum += __expf(x - m);
        }
    }
    float inv = 1.f / sum;
    for (int r = lo; r < hi; r++)
        probs[(size_t)r * CC + c] = __expf(logits[(size_t)r * CC + c] - m) * inv;
}

// ===========================================================================
// Launch
// ===========================================================================
extern "C" void kernel_launch(void* const* d_in, const int* in_sizes, int n_in,
                              void* d_out, int out_size)
{
    const float* H  = nullptr;
    const int*   batch = nullptr;
    const float* W1 = nullptr;
    const float* b1 = nullptr;
    const float* W2 = nullptr;
    const float* b2 = nullptr;

    for (int i = 0; i < n_in; i++) {
        switch (in_sizes[i]) {
            case 128000000: H     = (const float*)d_in[i]; break;
            case 500000:    batch = (const int*)d_in[i];   break;
            case 65536:     W1    = (const float*)d_in[i]; break;
            case 256:       b1    = (const float*)d_in[i]; break;
            case 32768:     W2    = (const float*)d_in[i]; break;
            case 128:       b2    = (const float*)d_in[i]; break;
            default: break;
        }
    }

    float* out    = (float*)d_out;
    float* logits = out;                       // [NN, CC]
    float* probs  = out + (size_t)NN * CC;     // [NN, CC]

    void* h_sym = nullptr;
    cudaGetSymbolAddress(&h_sym, g_h);
    float* hbuf = (float*)h_sym;

    const int mblocks = (NN + BM - 1) / BM;    // 3907

    // Layer 1: h = relu(H @ W1 + b1)   [NN, 256]
    dim3 g1(mblocks, DD / BN);                 // 3907 x 4
    gemm_hmma<<<g1, 256>>>(H, W1, b1, hbuf, NN, DD, 1);

    // Layer 2: logits = h @ W2 + b2    [NN, 128]
    dim3 g2(mblocks, CC / BN);                 // 3907 x 2
    gemm_hmma<<<g2, 256>>>(hbuf, W2, b2, logits, NN, CC, 0);

    // Segment softmax -> probs
    seg_softmax<<<SSEG, 128>>>(logits, batch, probs);
}

// round 6
// speedup vs baseline: 1.7725x; 1.2734x over previous
#include <cuda_runtime.h>
#include <cuda_bf16.h>
#include <math_constants.h>
#include <cstdint>

#define NN 500000
#define DD 256
#define CC 128
#define SSEG 2048

#define BM 128
#define BN 128
#define BK 32
#define PITCH 136   // words per kk-row (128 + 8 pad) -> conflict-free frag loads

// Scratch for hidden activations h = relu(H@W1+b1): 500000*256 fp32 = 512 MB.
__device__ float g_h[(long long)NN * DD];

#define MMA16816(d, a, b)                                                     \
    asm volatile(                                                             \
        "mma.sync.aligned.m16n8k16.row.col.f32.bf16.bf16.f32 "                \
        "{%0,%1,%2,%3}, {%4,%5,%6,%7}, {%8,%9}, {%0,%1,%2,%3};"               \
        : "+f"((d)[0]), "+f"((d)[1]), "+f"((d)[2]), "+f"((d)[3])              \
        : "r"((a)[0]), "r"((a)[1]), "r"((a)[2]), "r"((a)[3]),                 \
          "r"((b)[0]), "r"((b)[1]))

__device__ __forceinline__ uint32_t pack_hi(float x, float y) {
    __nv_bfloat162 h = __floats2bfloat162_rn(x, y);
    return *reinterpret_cast<uint32_t*>(&h);
}
__device__ __forceinline__ uint32_t pack_lo(float x, float y) {
    __nv_bfloat162 h = __floats2bfloat162_rn(x, y);
    float rx = x - __low2float(h);
    float ry = y - __high2float(h);
    __nv_bfloat162 l = __floats2bfloat162_rn(rx, ry);
    return *reinterpret_cast<uint32_t*>(&l);
}

// ===========================================================================
// HMMA bf16-split GEMM: Cout[M,Nfull] = act(A[M,256] @ W[256,Nfull] + bias)
// CTA 128x128, 8 warps (2m x 4n), warp tile 64x32, K chunks of 32.
// 3 products per k16-step with fragment reuse: Ah*Bh + Ah*Bl + Al*Bh.
// ===========================================================================
__global__ __launch_bounds__(256, 2)
void gemm_hmma(const float* __restrict__ A, const float* __restrict__ W,
               const float* __restrict__ bias, float* __restrict__ Cout,
               int M, int Nfull, int relu)
{
    __shared__ uint32_t sAhi[16 * PITCH];
    __shared__ uint32_t sAlo[16 * PITCH];
    __shared__ uint32_t sBhi[16 * PITCH];
    __shared__ uint32_t sBlo[16 * PITCH];
    __shared__ float    sbias[BN];

    const int tid  = threadIdx.x;
    const int lane = tid & 31;
    const int wid  = tid >> 5;
    const int wm   = wid & 1;        // m offset wm*64
    const int wn   = wid >> 1;       // n offset wn*32
    const int gid  = lane >> 2;      // 0..7
    const int tig  = lane & 3;       // 0..3
    const int m0   = blockIdx.x * BM;
    const int n0   = blockIdx.y * BN;

    if (tid < BN) sbias[tid] = bias[n0 + tid];

    float acc[4][4][4];
#pragma unroll
    for (int mt = 0; mt < 4; mt++)
#pragma unroll
        for (int nt = 0; nt < 4; nt++)
#pragma unroll
            for (int i = 0; i < 4; i++) acc[mt][nt][i] = 0.f;

    // staging index maps
    const int am  = tid & 127;       // A: m row
    const int akq = tid >> 7;        // A: 0..1
    const int bkk = tid >> 5;        // B: 0..7 (warp-uniform)
    const int bn4 = tid & 31;        // B: n/4

#pragma unroll 1
    for (int c = 0; c < 8; c++) {
        const int k0 = c * BK;
        __syncthreads();             // smem consumed by previous chunk

        // ---- load gmem chunk into registers ----
        float4 ra[4];
#pragma unroll
        for (int l = 0; l < 4; l++) {
            int kq = akq + 2 * l;
            int grow = m0 + am;
            ra[l] = (grow < M)
                ? *reinterpret_cast<const float4*>(&A[(size_t)grow * DD + k0 + kq * 4])
                : make_float4(0.f, 0.f, 0.f, 0.f);
        }
        float4 rb[2][2];
#pragma unroll
        for (int l = 0; l < 2; l++) {
            int kk = bkk + 8 * l;
            rb[l][0] = *reinterpret_cast<const float4*>(&W[(size_t)(k0 + 2 * kk)     * Nfull + n0 + bn4 * 4]);
            rb[l][1] = *reinterpret_cast<const float4*>(&W[(size_t)(k0 + 2 * kk + 1) * Nfull + n0 + bn4 * 4]);
        }

        // ---- convert + store to SMEM ----
#pragma unroll
        for (int l = 0; l < 4; l++) {
            int kq = akq + 2 * l;
            float4 v = ra[l];
            sAhi[(2 * kq    ) * PITCH + am] = pack_hi(v.x, v.y);
            sAlo[(2 * kq    ) * PITCH + am] = pack_lo(v.x, v.y);
            sAhi[(2 * kq + 1) * PITCH + am] = pack_hi(v.z, v.w);
            sAlo[(2 * kq + 1) * PITCH + am] = pack_lo(v.z, v.w);
        }
#pragma unroll
        for (int l = 0; l < 2; l++) {
            int kk = bkk + 8 * l;
            uint4 ph, pl;
            ph.x = pack_hi(rb[l][0].x, rb[l][1].x);  pl.x = pack_lo(rb[l][0].x, rb[l][1].x);
            ph.y = pack_hi(rb[l][0].y, rb[l][1].y);  pl.y = pack_lo(rb[l][0].y, rb[l][1].y);
            ph.z = pack_hi(rb[l][0].z, rb[l][1].z);  pl.z = pack_lo(rb[l][0].z, rb[l][1].z);
            ph.w = pack_hi(rb[l][0].w, rb[l][1].w);  pl.w = pack_lo(rb[l][0].w, rb[l][1].w);
            *reinterpret_cast<uint4*>(&sBhi[kk * PITCH + bn4 * 4]) = ph;
            *reinterpret_cast<uint4*>(&sBlo[kk * PITCH + bn4 * 4]) = pl;
        }
        __syncthreads();

        // ---- compute: load fragments once, run 3 products ----
#pragma unroll
        for (int s = 0; s < 2; s++) {
            const int kk = s * 8 + tig;
            uint32_t afh[4][4], afl[4][4], bfh[4][2], bfl[4][2];
#pragma unroll
            for (int mt = 0; mt < 4; mt++) {
                int mrow = wm * 64 + mt * 16 + gid;
                afh[mt][0] = sAhi[(kk    ) * PITCH + mrow];
                afh[mt][1] = sAhi[(kk    ) * PITCH + mrow + 8];
                afh[mt][2] = sAhi[(kk + 4) * PITCH + mrow];
                afh[mt][3] = sAhi[(kk + 4) * PITCH + mrow + 8];
                afl[mt][0] = sAlo[(kk    ) * PITCH + mrow];
                afl[mt][1] = sAlo[(kk    ) * PITCH + mrow + 8];
                afl[mt][2] = sAlo[(kk + 4) * PITCH + mrow];
                afl[mt][3] = sAlo[(kk + 4) * PITCH + mrow + 8];
            }
#pragma unroll
            for (int nt = 0; nt < 4; nt++) {
                int ncol = wn * 32 + nt * 8 + gid;
                bfh[nt][0] = sBhi[(kk    ) * PITCH + ncol];
                bfh[nt][1] = sBhi[(kk + 4) * PITCH + ncol];
                bfl[nt][0] = sBlo[(kk    ) * PITCH + ncol];
                bfl[nt][1] = sBlo[(kk + 4) * PITCH + ncol];
            }
#pragma unroll
            for (int mt = 0; mt < 4; mt++)
#pragma unroll
                for (int nt = 0; nt < 4; nt++)
                    MMA16816(acc[mt][nt], afh[mt], bfh[nt]);
#pragma unroll
            for (int mt = 0; mt < 4; mt++)
#pragma unroll
                for (int nt = 0; nt < 4; nt++)
                    MMA16816(acc[mt][nt], afh[mt], bfl[nt]);
#pragma unroll
            for (int mt = 0; mt < 4; mt++)
#pragma unroll
                for (int nt = 0; nt < 4; nt++)
                    MMA16816(acc[mt][nt], afl[mt], bfh[nt]);
        }
    }

    // ---- epilogue: bias (+ReLU), float2 stores ----
#pragma unroll
    for (int mt = 0; mt < 4; mt++) {
        int r0 = m0 + wm * 64 + mt * 16 + gid;
#pragma unroll
        for (int nt = 0; nt < 4; nt++) {
            int col = wn * 32 + nt * 8 + 2 * tig;
            float bv0 = sbias[col], bv1 = sbias[col + 1];
            float x0 = acc[mt][nt][0] + bv0;
            float x1 = acc[mt][nt][1] + bv1;
            float x2 = acc[mt][nt][2] + bv0;
            float x3 = acc[mt][nt][3] + bv1;
            if (relu) {
                x0 = fmaxf(x0, 0.f); x1 = fmaxf(x1, 0.f);
                x2 = fmaxf(x2, 0.f); x3 = fmaxf(x3, 0.f);
            }
            if (r0 < M)
                *reinterpret_cast<float2*>(&Cout[(size_t)r0 * Nfull + n0 + col]) =
                    make_float2(x0, x1);
            if (r0 + 8 < M)
                *reinterpret_cast<float2*>(&Cout[(size_t)(r0 + 8) * Nfull + n0 + col]) =
                    make_float2(x2, x3);
        }
    }
}

// ===========================================================================
// Segment softmax, online 2-pass. One block/segment, thread = class column.
// ===========================================================================
__device__ __forceinline__ int lower_bound_i32(const int* __restrict__ a,
                                               int n, int key)
{
    int lo = 0, hi = n;
    while (lo < hi) {
        int mid = (lo + hi) >> 1;
        if (a[mid] < key) lo = mid + 1; else hi = mid;
    }
    return lo;
}

__global__ __launch_bounds__(128) void seg_softmax(
    const float* __restrict__ logits,
    const int* __restrict__ batch,
    float* __restrict__ probs)
{
    const int s  = blockIdx.x;
    const int lo = lower_bound_i32(batch, NN, s);
    const int hi = lower_bound_i32(batch, NN, s + 1);
    const int c  = threadIdx.x;
    if (lo >= hi) return;

    float m = -CUDART_INF_F, sum = 0.f;
    for (int r = lo; r < hi; r++) {
        float x = logits[(size_t)r * CC + c];
        if (x > m) {
            sum = sum * __expf(m - x) + 1.f;
            m = x;
        } else {
            sum += __expf(x - m);
        }
    }
    float inv = 1.f / sum;
    for (int r = lo; r < hi; r++)
        probs[(size_t)r * CC + c] = __expf(logits[(size_t)r * CC + c] - m) * inv;
}

// ===========================================================================
// Launch
// ===========================================================================
extern "C" void kernel_launch(void* const* d_in, const int* in_sizes, int n_in,
                              void* d_out, int out_size)
{
    const float* H  = nullptr;
    const int*   batch = nullptr;
    const float* W1 = nullptr;
    const float* b1 = nullptr;
    const float* W2 = nullptr;
    const float* b2 = nullptr;

    for (int i = 0; i < n_in; i++) {
        switch (in_sizes[i]) {
            case 128000000: H     = (const float*)d_in[i]; break;
            case 500000:    batch = (const int*)d_in[i];   break;
            case 65536:     W1    = (const float*)d_in[i]; break;
            case 256:       b1    = (const float*)d_in[i]; break;
            case 32768:     W2    = (const float*)d_in[i]; break;
            case 128:       b2    = (const float*)d_in[i]; break;
            default: break;
        }
    }

    float* out    = (float*)d_out;
    float* logits = out;                       // [NN, CC]
    float* probs  = out + (size_t)NN * CC;     // [NN, CC]

    void* h_sym = nullptr;
    cudaGetSymbolAddress(&h_sym, g_h);
    float* hbuf = (float*)h_sym;

    const int mblocks = (NN + BM - 1) / BM;    // 3907

    // Layer 1: h = relu(H @ W1 + b1)   [NN, 256]
    dim3 g1(mblocks, DD / BN);                 // 3907 x 2
    gemm_hmma<<<g1, 256>>>(H, W1, b1, hbuf, NN, DD, 1);

    // Layer 2: logits = h @ W2 + b2    [NN, 128]
    dim3 g2(mblocks, CC / BN);                 // 3907 x 1
    gemm_hmma<<<g2, 256>>>(hbuf, W2, b2, logits, NN, CC, 0);

    // Segment softmax -> probs
    seg_softmax<<<SSEG, 128>>>(logits, batch, probs);
}

// round 7
// speedup vs baseline: 2.0953x; 1.1821x over previous
#include <cuda_runtime.h>
#include <cuda_bf16.h>
#include <math_constants.h>
#include <cstdint>

#define NN 500000
#define DD 256
#define CC 128
#define SSEG 2048

#define BM 128
#define BN 128
#define BK 32
#define PA 40        // A row pitch (floats): pitch%32==8 -> conflict-free LDS.64 frags
#define PB 132       // B row pitch (floats): pitch%32==4 -> conflict-free LDS.32 frags

// smem float offsets
#define SA_OFF(s)  ((s) * (BM * PA))                 // 2 stages: 0, 5120
#define SB_OFF(s)  (2 * BM * PA + (s) * (BK * PB))   // 10240 + s*4224
#define BIAS_OFF   (2 * BM * PA + 2 * BK * PB)       // 18688
#define SMEM_FLOATS (BIAS_OFF + BN)                  // 18816
#define SMEM_BYTES  (SMEM_FLOATS * 4)                // 75264

// Scratch for hidden activations h = relu(H@W1+b1): 500000*256 fp32 = 512 MB.
__device__ float g_h[(long long)NN * DD];

#define MMA16816(d, a, b)                                                     \
    asm volatile(                                                             \
        "mma.sync.aligned.m16n8k16.row.col.f32.bf16.bf16.f32 "                \
        "{%0,%1,%2,%3}, {%4,%5,%6,%7}, {%8,%9}, {%0,%1,%2,%3};"               \
        : "+f"((d)[0]), "+f"((d)[1]), "+f"((d)[2]), "+f"((d)[3])              \
        : "r"((a)[0]), "r"((a)[1]), "r"((a)[2]), "r"((a)[3]),                 \
          "r"((b)[0]), "r"((b)[1]))

__device__ __forceinline__ uint32_t pack_hi(float x, float y) {
    __nv_bfloat162 h = __floats2bfloat162_rn(x, y);
    return *reinterpret_cast<uint32_t*>(&h);
}
__device__ __forceinline__ uint32_t pack_lo(float x, float y) {
    __nv_bfloat162 h = __floats2bfloat162_rn(x, y);
    float rx = x - __low2float(h);
    float ry = y - __high2float(h);
    __nv_bfloat162 l = __floats2bfloat162_rn(rx, ry);
    return *reinterpret_cast<uint32_t*>(&l);
}

__device__ __forceinline__ void cpa16(uint32_t dst, const void* src, int srcsz) {
    asm volatile("cp.async.cg.shared.global [%0], [%1], 16, %2;"
                 :: "r"(dst), "l"(src), "r"(srcsz));
}
#define CP_COMMIT()  asm volatile("cp.async.commit_group;" ::: "memory")
#define CP_WAIT0()   asm volatile("cp.async.wait_group 0;" ::: "memory")

// ===========================================================================
// HMMA bf16-split GEMM with cp.async fp32 staging.
// Cout[M,Nfull] = act(A[M,256] @ W[256,Nfull] + bias)
// CTA 128x128, 8 warps (2m x 4n), warp tile 64x32, K chunks of 32, 2 stages.
// Convert fp32->bf16 hi/lo in registers at fragment-load time.
// ===========================================================================
__global__ __launch_bounds__(256, 2)
void gemm_hmma(const float* __restrict__ A, const float* __restrict__ W,
               const float* __restrict__ bias, float* __restrict__ Cout,
               int M, int Nfull, int relu)
{
    extern __shared__ float smem[];
    const uint32_t smem32 = (uint32_t)__cvta_generic_to_shared(smem);

    const int tid  = threadIdx.x;
    const int lane = tid & 31;
    const int wid  = tid >> 5;
    const int wm   = wid & 1;        // m offset wm*64
    const int wn   = wid >> 1;       // n offset wn*32
    const int gid  = lane >> 2;      // 0..7
    const int tig  = lane & 3;       // 0..3
    const int m0   = blockIdx.x * BM;
    const int n0   = blockIdx.y * BN;

    if (tid < BN) smem[BIAS_OFF + tid] = bias[n0 + tid];

    float acc[4][4][4];
#pragma unroll
    for (int mt = 0; mt < 4; mt++)
#pragma unroll
        for (int nt = 0; nt < 4; nt++)
#pragma unroll
            for (int i = 0; i < 4; i++) acc[mt][nt][i] = 0.f;

    // cp.async index maps
    const int arow = tid >> 1;              // 0..127 (A: 2 threads/row, 4 segs... )
    // A: 1024 x 16B ops/chunk, 4/thread: o = tid + 256*l -> row=o>>3, seg=o&7
    // B: 1024 x 16B ops/chunk, 4/thread: o = tid + 256*l -> row=o>>5, seg=o&31
    (void)arow;

    auto issue_chunk = [&](int c, int stg) {
        const int k0 = c * BK;
#pragma unroll
        for (int l = 0; l < 4; l++) {
            int o   = tid + 256 * l;
            int row = o >> 3;
            int seg = o & 7;
            int grow = m0 + row;
            uint32_t dst = smem32 + (uint32_t)(SA_OFF(stg) + row * PA + seg * 4) * 4u;
            // clamp src row to stay in-bounds; src_size=0 zero-fills when OOB
            const float* src = &A[(size_t)(grow < M ? grow : 0) * DD + k0 + seg * 4];
            cpa16(dst, src, (grow < M) ? 16 : 0);
        }
#pragma unroll
        for (int l = 0; l < 4; l++) {
            int o   = tid + 256 * l;
            int row = o >> 5;
            int seg = o & 31;
            uint32_t dst = smem32 + (uint32_t)(SB_OFF(stg) + row * PB + seg * 4) * 4u;
            cpa16(dst, &W[(size_t)(k0 + row) * Nfull + n0 + seg * 4], 16);
        }
        CP_COMMIT();
    };

    issue_chunk(0, 0);

#pragma unroll 1
    for (int c = 0; c < 8; c++) {
        CP_WAIT0();
        __syncthreads();
        if (c < 7) issue_chunk(c + 1, (c + 1) & 1);

        const float* sAc = smem + SA_OFF(c & 1);
        const float* sBc = smem + SB_OFF(c & 1);

#pragma unroll
        for (int s = 0; s < 2; s++) {
            // ---- B fragments (held across all mt): convert fp32 -> hi/lo ----
            uint32_t bfh[4][2], bfl[4][2];
#pragma unroll
            for (int nt = 0; nt < 4; nt++) {
                int ncol = wn * 32 + nt * 8 + gid;
#pragma unroll
                for (int p = 0; p < 2; p++) {
                    int k = 16 * s + 2 * tig + 8 * p;
                    float x0 = sBc[(k    ) * PB + ncol];
                    float x1 = sBc[(k + 1) * PB + ncol];
                    bfh[nt][p] = pack_hi(x0, x1);
                    bfl[nt][p] = pack_lo(x0, x1);
                }
            }
            // ---- per-mt: load A fp32 pairs, convert, 12 MMAs ----
#pragma unroll
            for (int mt = 0; mt < 4; mt++) {
                int mrow = wm * 64 + mt * 16 + gid;
                int kb   = 16 * s + 2 * tig;
                float2 f0 = *reinterpret_cast<const float2*>(&sAc[(mrow    ) * PA + kb    ]);
                float2 f1 = *reinterpret_cast<const float2*>(&sAc[(mrow + 8) * PA + kb    ]);
                float2 f2 = *reinterpret_cast<const float2*>(&sAc[(mrow    ) * PA + kb + 8]);
                float2 f3 = *reinterpret_cast<const float2*>(&sAc[(mrow + 8) * PA + kb + 8]);
                uint32_t afh[4], afl[4];
                afh[0] = pack_hi(f0.x, f0.y);  afl[0] = pack_lo(f0.x, f0.y);
                afh[1] = pack_hi(f1.x, f1.y);  afl[1] = pack_lo(f1.x, f1.y);
                afh[2] = pack_hi(f2.x, f2.y);  afl[2] = pack_lo(f2.x, f2.y);
                afh[3] = pack_hi(f3.x, f3.y);  afl[3] = pack_lo(f3.x, f3.y);
#pragma unroll
                for (int nt = 0; nt < 4; nt++)
                    MMA16816(acc[mt][nt], afh, bfh[nt]);
#pragma unroll
                for (int nt = 0; nt < 4; nt++)
                    MMA16816(acc[mt][nt], afh, bfl[nt]);
#pragma unroll
                for (int nt = 0; nt < 4; nt++)
                    MMA16816(acc[mt][nt], afl, bfh[nt]);
            }
        }
    }

    // ---- epilogue: bias (+ReLU), float2 stores ----
    const float* sbias = smem + BIAS_OFF;
#pragma unroll
    for (int mt = 0; mt < 4; mt++) {
        int r0 = m0 + wm * 64 + mt * 16 + gid;
#pragma unroll
        for (int nt = 0; nt < 4; nt++) {
            int col = wn * 32 + nt * 8 + 2 * tig;
            float bv0 = sbias[col], bv1 = sbias[col + 1];
            float x0 = acc[mt][nt][0] + bv0;
            float x1 = acc[mt][nt][1] + bv1;
            float x2 = acc[mt][nt][2] + bv0;
            float x3 = acc[mt][nt][3] + bv1;
            if (relu) {
                x0 = fmaxf(x0, 0.f); x1 = fmaxf(x1, 0.f);
                x2 = fmaxf(x2, 0.f); x3 = fmaxf(x3, 0.f);
            }
            if (r0 < M)
                *reinterpret_cast<float2*>(&Cout[(size_t)r0 * Nfull + n0 + col]) =
                    make_float2(x0, x1);
            if (r0 + 8 < M)
                *reinterpret_cast<float2*>(&Cout[(size_t)(r0 + 8) * Nfull + n0 + col]) =
                    make_float2(x2, x3);
        }
    }
}

// ===========================================================================
// Segment softmax, online 2-pass. One block/segment, thread = class column.
// ===========================================================================
__device__ __forceinline__ int lower_bound_i32(const int* __restrict__ a,
                                               int n, int key)
{
    int lo = 0, hi = n;
    while (lo < hi) {
        int mid = (lo + hi) >> 1;
        if (a[mid] < key) lo = mid + 1; else hi = mid;
    }
    return lo;
}

__global__ __launch_bounds__(128) void seg_softmax(
    const float* __restrict__ logits,
    const int* __restrict__ batch,
    float* __restrict__ probs)
{
    const int s  = blockIdx.x;
    const int lo = lower_bound_i32(batch, NN, s);
    const int hi = lower_bound_i32(batch, NN, s + 1);
    const int c  = threadIdx.x;
    if (lo >= hi) return;

    float m = -CUDART_INF_F, sum = 0.f;
    for (int r = lo; r < hi; r++) {
        float x = logits[(size_t)r * CC + c];
        if (x > m) {
            sum = sum * __expf(m - x) + 1.f;
            m = x;
        } else {
            sum += __expf(x - m);
        }
    }
    float inv = 1.f / sum;
    for (int r = lo; r < hi; r++)
        probs[(size_t)r * CC + c] = __expf(logits[(size_t)r * CC + c] - m) * inv;
}

// ===========================================================================
// Launch
// ===========================================================================
extern "C" void kernel_launch(void* const* d_in, const int* in_sizes, int n_in,
                              void* d_out, int out_size)
{
    const float* H  = nullptr;
    const int*   batch = nullptr;
    const float* W1 = nullptr;
    const float* b1 = nullptr;
    const float* W2 = nullptr;
    const float* b2 = nullptr;

    for (int i = 0; i < n_in; i++) {
        switch (in_sizes[i]) {
            case 128000000: H     = (const float*)d_in[i]; break;
            case 500000:    batch = (const int*)d_in[i];   break;
            case 65536:     W1    = (const float*)d_in[i]; break;
            case 256:       b1    = (const float*)d_in[i]; break;
            case 32768:     W2    = (const float*)d_in[i]; break;
            case 128:       b2    = (const float*)d_in[i]; break;
            default: break;
        }
    }

    float* out    = (float*)d_out;
    float* logits = out;                       // [NN, CC]
    float* probs  = out + (size_t)NN * CC;     // [NN, CC]

    void* h_sym = nullptr;
    cudaGetSymbolAddress(&h_sym, g_h);
    float* hbuf = (float*)h_sym;

    static int attr_set = 0;
    if (!attr_set) {
        cudaFuncSetAttribute(gemm_hmma,
                             cudaFuncAttributeMaxDynamicSharedMemorySize, SMEM_BYTES);
        attr_set = 1;
    }

    const int mblocks = (NN + BM - 1) / BM;    // 3907

    // Layer 1: h = relu(H @ W1 + b1)   [NN, 256]
    dim3 g1(mblocks, DD / BN);                 // 3907 x 2
    gemm_hmma<<<g1, 256, SMEM_BYTES>>>(H, W1, b1, hbuf, NN, DD, 1);

    // Layer 2: logits = h @ W2 + b2    [NN, 128]
    dim3 g2(mblocks, CC / BN);                 // 3907 x 1
    gemm_hmma<<<g2, 256, SMEM_BYTES>>>(hbuf, W2, b2, logits, NN, CC, 0);

    // Segment softmax -> probs
    seg_softmax<<<SSEG, 128>>>(logits, batch, probs);
}

// round 8
// speedup vs baseline: 2.3226x; 1.1085x over previous
#include <cuda_runtime.h>
#include <cuda_bf16.h>
#include <math_constants.h>
#include <cstdint>

#define NN 500000
#define DD 256
#define CC 128
#define SSEG 2048

#define BM 128
#define BN 128
#define BK 32
#define PA 40    // A fp32 pitch (floats): %32==8 -> conflict-free LDS.64 frags
#define PAW 20   // A bf16-word pitch: lane bank = (gid*20+tig)%32, all distinct
#define PBW 136  // B word pitch: lane bank = (tig*8+gid)%32, all distinct

// smem word offsets (uniform across both variants; 19072 words = 76288 B)
#define SA_OFF(s)   ((s) * 5120)            // fp32 A: 128*40
#define SAH_OFF(s)  ((s) * 2560)            // bf16 A hi: 128*20
#define SAL_OFF(s)  (5120 + (s) * 2560)     // bf16 A lo
#define SBH_OFF(s)  (10240 + (s) * 2176)    // B hi: 16*136
#define SBL_OFF(s)  (14592 + (s) * 2176)    // B lo
#define BIAS_OFF    18944
#define SMEM_BYTES  (19072 * 4)

// h stored as packed bf16 hi/lo words [m][kp], 128 words/row: 2x256 MB.
__device__ uint32_t g_hhi[(long long)NN * 128];
__device__ uint32_t g_hlo[(long long)NN * 128];
// pre-converted weights, word layout [kp][n]
__device__ uint32_t g_w1hi[128 * 256], g_w1lo[128 * 256];
__device__ uint32_t g_w2hi[128 * 128], g_w2lo[128 * 128];

#define MMA16816(d, a, b)                                                     \
    asm volatile(                                                             \
        "mma.sync.aligned.m16n8k16.row.col.f32.bf16.bf16.f32 "                \
        "{%0,%1,%2,%3}, {%4,%5,%6,%7}, {%8,%9}, {%0,%1,%2,%3};"               \
        : "+f"((d)[0]), "+f"((d)[1]), "+f"((d)[2]), "+f"((d)[3])              \
        : "r"((a)[0]), "r"((a)[1]), "r"((a)[2]), "r"((a)[3]),                 \
          "r"((b)[0]), "r"((b)[1]))

__device__ __forceinline__ void pack2(float x, float y, uint32_t& hi, uint32_t& lo) {
    __nv_bfloat162 h = __floats2bfloat162_rn(x, y);
    hi = *reinterpret_cast<uint32_t*>(&h);
    float rx = x - __low2float(h);
    float ry = y - __high2float(h);
    __nv_bfloat162 l = __floats2bfloat162_rn(rx, ry);
    lo = *reinterpret_cast<uint32_t*>(&l);
}

__device__ __forceinline__ void cpa16(uint32_t dst, const void* src, int srcsz) {
    asm volatile("cp.async.cg.shared.global [%0], [%1], 16, %2;"
                 :: "r"(dst), "l"(src), "r"(srcsz));
}
#define CP_COMMIT()  asm volatile("cp.async.commit_group;" ::: "memory")
#define CP_WAIT0()   asm volatile("cp.async.wait_group 0;" ::: "memory")

// ===========================================================================
// Weight pre-conversion: W[k][n] fp32 -> packed hi/lo words [kp][n]
// ===========================================================================
__global__ __launch_bounds__(256) void convert_w(
    const float* __restrict__ W1, const float* __restrict__ W2)
{
    int idx = blockIdx.x * 256 + threadIdx.x;
    if (idx < 128 * 256) {
        int kp = idx >> 8, n = idx & 255;
        uint32_t hi, lo;
        pack2(W1[(2 * kp) * 256 + n], W1[(2 * kp + 1) * 256 + n], hi, lo);
        g_w1hi[idx] = hi; g_w1lo[idx] = lo;
    } else {
        int j = idx - 128 * 256;
        if (j < 128 * 128) {
            int kp = j >> 7, n = j & 127;
            uint32_t hi, lo;
            pack2(W2[(2 * kp) * 128 + n], W2[(2 * kp + 1) * 128 + n], hi, lo);
            g_w2hi[j] = hi; g_w2lo[j] = lo;
        }
    }
}

// ===========================================================================
// HMMA bf16-split GEMM. ABF16: A operand is pre-split bf16 (hi/lo word arrays)
// vs fp32 (converted at fragment-load). WHL: write output as packed hi/lo
// bf16 words (for h) vs fp32 (logits).
// CTA 128x128, 8 warps (2m x 4n), warp tile 64x32, BK=32, 2-stage cp.async.
// ===========================================================================
template <int ABF16, int WHL>
__global__ __launch_bounds__(256, 2)
void gemm_hmma(const float* __restrict__ A32,
               const uint32_t* __restrict__ Ahi, const uint32_t* __restrict__ Alo,
               const uint32_t* __restrict__ Bhi, const uint32_t* __restrict__ Blo,
               const float* __restrict__ bias,
               float* __restrict__ Cout,
               uint32_t* __restrict__ Chi, uint32_t* __restrict__ Clo,
               int M, int Nfull, int relu)
{
    extern __shared__ float smem[];
    uint32_t* smw = reinterpret_cast<uint32_t*>(smem);
    const uint32_t smem32 = (uint32_t)__cvta_generic_to_shared(smem);

    const int tid  = threadIdx.x;
    const int lane = tid & 31;
    const int wid  = tid >> 5;
    const int wm   = wid & 1;
    const int wn   = wid >> 1;
    const int gid  = lane >> 2;
    const int tig  = lane & 3;
    const int m0   = blockIdx.x * BM;
    const int n0   = blockIdx.y * BN;

    if (tid < BN) smem[BIAS_OFF + tid] = bias[n0 + tid];

    float acc[4][4][4];
#pragma unroll
    for (int mt = 0; mt < 4; mt++)
#pragma unroll
        for (int nt = 0; nt < 4; nt++)
#pragma unroll
            for (int i = 0; i < 4; i++) acc[mt][nt][i] = 0.f;

    auto issue_chunk = [&](int c, int stg) {
        const int k0 = c * BK;
        if (ABF16) {
            // A: bf16 hi/lo words [m][128], 2048 words per array per chunk
#pragma unroll
            for (int l = 0; l < 2; l++) {
                int o = tid + 256 * l;
                int row = o >> 2, seg = o & 3;
                int grow = m0 + row;
                int ok = (grow < M);
                const uint32_t* sh = &Ahi[(size_t)(ok ? grow : 0) * 128 + c * 16 + seg * 4];
                const uint32_t* sl = &Alo[(size_t)(ok ? grow : 0) * 128 + c * 16 + seg * 4];
                cpa16(smem32 + (uint32_t)(SAH_OFF(stg) + row * PAW + seg * 4) * 4u, sh, ok ? 16 : 0);
                cpa16(smem32 + (uint32_t)(SAL_OFF(stg) + row * PAW + seg * 4) * 4u, sl, ok ? 16 : 0);
            }
        } else {
            // A: fp32 [m][256]
#pragma unroll
            for (int l = 0; l < 4; l++) {
                int o = tid + 256 * l;
                int row = o >> 3, seg = o & 7;
                int grow = m0 + row;
                int ok = (grow < M);
                const float* src = &A32[(size_t)(ok ? grow : 0) * DD + k0 + seg * 4];
                cpa16(smem32 + (uint32_t)(SA_OFF(stg) + row * PA + seg * 4) * 4u, src, ok ? 16 : 0);
            }
        }
        // B: hi/lo words [kp][Nfull], 16 rows x 128 cols per chunk
#pragma unroll
        for (int l = 0; l < 2; l++) {
            int o = tid + 256 * l;
            int row = o >> 5, seg = o & 31;
            cpa16(smem32 + (uint32_t)(SBH_OFF(stg) + row * PBW + seg * 4) * 4u,
                  &Bhi[(size_t)(c * 16 + row) * Nfull + n0 + seg * 4], 16);
            cpa16(smem32 + (uint32_t)(SBL_OFF(stg) + row * PBW + seg * 4) * 4u,
                  &Blo[(size_t)(c * 16 + row) * Nfull + n0 + seg * 4], 16);
        }
        CP_COMMIT();
    };

    issue_chunk(0, 0);

#pragma unroll 1
    for (int c = 0; c < 8; c++) {
        CP_WAIT0();
        __syncthreads();
        if (c < 7) issue_chunk(c + 1, (c + 1) & 1);

        const int stg = c & 1;

#pragma unroll
        for (int s = 0; s < 2; s++) {
            // ---- B fragments: direct packed-word loads ----
            uint32_t bfh[4][2], bfl[4][2];
            const int kpb = 8 * s + tig;
#pragma unroll
            for (int nt = 0; nt < 4; nt++) {
                int ncol = wn * 32 + nt * 8 + gid;
                bfh[nt][0] = smw[SBH_OFF(stg) + (kpb    ) * PBW + ncol];
                bfh[nt][1] = smw[SBH_OFF(stg) + (kpb + 4) * PBW + ncol];
                bfl[nt][0] = smw[SBL_OFF(stg) + (kpb    ) * PBW + ncol];
                bfl[nt][1] = smw[SBL_OFF(stg) + (kpb + 4) * PBW + ncol];
            }
#pragma unroll
            for (int mt = 0; mt < 4; mt++) {
                int mrow = wm * 64 + mt * 16 + gid;
                uint32_t afh[4], afl[4];
                if (ABF16) {
                    const int kpa = 8 * s + tig;
                    afh[0] = smw[SAH_OFF(stg) + (mrow    ) * PAW + kpa    ];
                    afh[1] = smw[SAH_OFF(stg) + (mrow + 8) * PAW + kpa    ];
                    afh[2] = smw[SAH_OFF(stg) + (mrow    ) * PAW + kpa + 4];
                    afh[3] = smw[SAH_OFF(stg) + (mrow + 8) * PAW + kpa + 4];
                    afl[0] = smw[SAL_OFF(stg) + (mrow    ) * PAW + kpa    ];
                    afl[1] = smw[SAL_OFF(stg) + (mrow + 8) * PAW + kpa    ];
                    afl[2] = smw[SAL_OFF(stg) + (mrow    ) * PAW + kpa + 4];
                    afl[3] = smw[SAL_OFF(stg) + (mrow + 8) * PAW + kpa + 4];
                } else {
                    const float* sAc = smem + SA_OFF(stg);
                    int kb = 16 * s + 2 * tig;
                    float2 f0 = *reinterpret_cast<const float2*>(&sAc[(mrow    ) * PA + kb    ]);
                    float2 f1 = *reinterpret_cast<const float2*>(&sAc[(mrow + 8) * PA + kb    ]);
                    float2 f2 = *reinterpret_cast<const float2*>(&sAc[(mrow    ) * PA + kb + 8]);
                    float2 f3 = *reinterpret_cast<const float2*>(&sAc[(mrow + 8) * PA + kb + 8]);
                    pack2(f0.x, f0.y, afh[0], afl[0]);
                    pack2(f1.x, f1.y, afh[1], afl[1]);
                    pack2(f2.x, f2.y, afh[2], afl[2]);
                    pack2(f3.x, f3.y, afh[3], afl[3]);
                }
#pragma unroll
                for (int nt = 0; nt < 4; nt++)
                    MMA16816(acc[mt][nt], afh, bfh[nt]);
#pragma unroll
                for (int nt = 0; nt < 4; nt++)
                    MMA16816(acc[mt][nt], afh, bfl[nt]);
#pragma unroll
                for (int nt = 0; nt < 4; nt++)
                    MMA16816(acc[mt][nt], afl, bfh[nt]);
            }
        }
    }

    // ---- epilogue ----
    const float* sbias = smem + BIAS_OFF;
#pragma unroll
    for (int mt = 0; mt < 4; mt++) {
        int r0 = m0 + wm * 64 + mt * 16 + gid;
#pragma unroll
        for (int nt = 0; nt < 4; nt++) {
            int col = wn * 32 + nt * 8 + 2 * tig;
            float bv0 = sbias[col], bv1 = sbias[col + 1];
            float x0 = acc[mt][nt][0] + bv0;
            float x1 = acc[mt][nt][1] + bv1;
            float x2 = acc[mt][nt][2] + bv0;
            float x3 = acc[mt][nt][3] + bv1;
            if (relu) {
                x0 = fmaxf(x0, 0.f); x1 = fmaxf(x1, 0.f);
                x2 = fmaxf(x2, 0.f); x3 = fmaxf(x3, 0.f);
            }
            if (WHL) {
                // write packed hi/lo words; (col, col+1) is a k-pair for layer 2
                int wcol = (n0 + col) >> 1;
                if (r0 < M) {
                    uint32_t hi, lo;
                    pack2(x0, x1, hi, lo);
                    Chi[(size_t)r0 * 128 + wcol] = hi;
                    Clo[(size_t)r0 * 128 + wcol] = lo;
                }
                if (r0 + 8 < M) {
                    uint32_t hi, lo;
                    pack2(x2, x3, hi, lo);
                    Chi[(size_t)(r0 + 8) * 128 + wcol] = hi;
                    Clo[(size_t)(r0 + 8) * 128 + wcol] = lo;
                }
            } else {
                if (r0 < M)
                    *reinterpret_cast<float2*>(&Cout[(size_t)r0 * Nfull + n0 + col]) =
                        make_float2(x0, x1);
                if (r0 + 8 < M)
                    *reinterpret_cast<float2*>(&Cout[(size_t)(r0 + 8) * Nfull + n0 + col]) =
                        make_float2(x2, x3);
            }
        }
    }
}

// ===========================================================================
// Segment softmax, online 2-pass. One block/segment, thread = class column.
// ===========================================================================
__device__ __forceinline__ int lower_bound_i32(const int* __restrict__ a,
                                               int n, int key)
{
    int lo = 0, hi = n;
    while (lo < hi) {
        int mid = (lo + hi) >> 1;
        if (a[mid] < key) lo = mid + 1; else hi = mid;
    }
    return lo;
}

__global__ __launch_bounds__(128) void seg_softmax(
    const float* __restrict__ logits,
    const int* __restrict__ batch,
    float* __restrict__ probs)
{
    const int s  = blockIdx.x;
    const int lo = lower_bound_i32(batch, NN, s);
    const int hi = lower_bound_i32(batch, NN, s + 1);
    const int c  = threadIdx.x;
    if (lo >= hi) return;

    float m = -CUDART_INF_F, sum = 0.f;
    for (int r = lo; r < hi; r++) {
        float x = logits[(size_t)r * CC + c];
        if (x > m) {
            sum = sum * __expf(m - x) + 1.f;
            m = x;
        } else {
            sum += __expf(x - m);
        }
    }
    float inv = 1.f / sum;
    for (int r = lo; r < hi; r++)
        probs[(size_t)r * CC + c] = __expf(logits[(size_t)r * CC + c] - m) * inv;
}

// ===========================================================================
// Launch
// ===========================================================================
extern "C" void kernel_launch(void* const* d_in, const int* in_sizes, int n_in,
                              void* d_out, int out_size)
{
    const float* H  = nullptr;
    const int*   batch = nullptr;
    const float* W1 = nullptr;
    const float* b1 = nullptr;
    const float* W2 = nullptr;
    const float* b2 = nullptr;

    for (int i = 0; i < n_in; i++) {
        switch (in_sizes[i]) {
            case 128000000: H     = (const float*)d_in[i]; break;
            case 500000:    batch = (const int*)d_in[i];   break;
            case 65536:     W1    = (const float*)d_in[i]; break;
            case 256:       b1    = (const float*)d_in[i]; break;
            case 32768:     W2    = (const float*)d_in[i]; break;
            case 128:       b2    = (const float*)d_in[i]; break;
            default: break;
        }
    }

    float* out    = (float*)d_out;
    float* logits = out;
    float* probs  = out + (size_t)NN * CC;

    void *hhi, *hlo, *w1hi, *w1lo, *w2hi, *w2lo;
    cudaGetSymbolAddress(&hhi, g_hhi);
    cudaGetSymbolAddress(&hlo, g_hlo);
    cudaGetSymbolAddress(&w1hi, g_w1hi);
    cudaGetSymbolAddress(&w1lo, g_w1lo);
    cudaGetSymbolAddress(&w2hi, g_w2hi);
    cudaGetSymbolAddress(&w2lo, g_w2lo);

    cudaFuncSetAttribute(gemm_hmma<0, 1>,
                         cudaFuncAttributeMaxDynamicSharedMemorySize, SMEM_BYTES);
    cudaFuncSetAttribute(gemm_hmma<1, 0>,
                         cudaFuncAttributeMaxDynamicSharedMemorySize, SMEM_BYTES);

    // Pre-convert weights (tiny)
    convert_w<<<192, 256>>>(W1, W2);

    const int mblocks = (NN + BM - 1) / BM;    // 3907

    // Layer 1: h = relu(H @ W1 + b1), written as packed hi/lo bf16 words
    dim3 g1(mblocks, DD / BN);                 // 3907 x 2
    gemm_hmma<0, 1><<<g1, 256, SMEM_BYTES>>>(
        H, nullptr, nullptr, (const uint32_t*)w1hi, (const uint32_t*)w1lo,
        b1, nullptr, (uint32_t*)hhi, (uint32_t*)hlo, NN, DD, 1);

    // Layer 2: logits = h @ W2 + b2 (fp32 out)
    dim3 g2(mblocks, CC / BN);                 // 3907 x 1
    gemm_hmma<1, 0><<<g2, 256, SMEM_BYTES>>>(
        nullptr, (const uint32_t*)hhi, (const uint32_t*)hlo,
        (const uint32_t*)w2hi, (const uint32_t*)w2lo,
        b2, logits, nullptr, nullptr, NN, CC, 0);

    // Segment softmax -> probs
    seg_softmax<<<SSEG, 128>>>(logits, batch, probs);
}

// round 9
// speedup vs baseline: 2.3830x; 1.0260x over previous
#include <cuda_runtime.h>
#include <cuda_bf16.h>
#include <math_constants.h>
#include <cstdint>

#define NN 500000
#define DD 256
#define CC 128
#define SSEG 2048

#define PA  40    // H fp32 stage pitch (floats): %32==8 -> conflict-free LDS.64
#define PBW 136   // B word pitch: %32==8 -> banks tig*8+gid, all distinct
#define PH  132   // h word pitch: %32==4 -> banks gid*4+tig, all distinct

// smem word offsets
#define SA_OFF(s)   ((s) * 5120)            // H fp32: 128*40, 2 stages
#define SBH_OFF(s)  (10240 + (s) * 2176)    // B hi: 16*136, 2 stages
#define SBL_OFF(s)  (14592 + (s) * 2176)    // B lo
#define HH_OFF      18944                   // h hi: 128*132
#define HL_OFF      35840                   // h lo: 128*132
#define B1_OFF      52736                   // b1: 256 floats
#define B2_OFF      52992                   // b2: 128 floats
#define SMEM_WORDS  53120
#define SMEM_BYTES  (SMEM_WORDS * 4)        // 212480 B -> 1 CTA/SM

// pre-converted weights, word layout [kp][n]
__device__ uint32_t g_w1hi[128 * 256], g_w1lo[128 * 256];
__device__ uint32_t g_w2hi[128 * 128], g_w2lo[128 * 128];

#define MMA16816(d, a, b)                                                     \
    asm volatile(                                                             \
        "mma.sync.aligned.m16n8k16.row.col.f32.bf16.bf16.f32 "                \
        "{%0,%1,%2,%3}, {%4,%5,%6,%7}, {%8,%9}, {%0,%1,%2,%3};"               \
        : "+f"((d)[0]), "+f"((d)[1]), "+f"((d)[2]), "+f"((d)[3])              \
        : "r"((a)[0]), "r"((a)[1]), "r"((a)[2]), "r"((a)[3]),                 \
          "r"((b)[0]), "r"((b)[1]))

__device__ __forceinline__ void pack2(float x, float y, uint32_t& hi, uint32_t& lo) {
    __nv_bfloat162 h = __floats2bfloat162_rn(x, y);
    hi = *reinterpret_cast<uint32_t*>(&h);
    float rx = x - __low2float(h);
    float ry = y - __high2float(h);
    __nv_bfloat162 l = __floats2bfloat162_rn(rx, ry);
    lo = *reinterpret_cast<uint32_t*>(&l);
}

__device__ __forceinline__ void cpa16(uint32_t dst, const void* src, int srcsz) {
    asm volatile("cp.async.cg.shared.global [%0], [%1], 16, %2;"
                 :: "r"(dst), "l"(src), "r"(srcsz));
}
#define CP_COMMIT()  asm volatile("cp.async.commit_group;" ::: "memory")
#define CP_WAIT0()   asm volatile("cp.async.wait_group 0;" ::: "memory")

// ===========================================================================
// Weight pre-conversion: W[k][n] fp32 -> packed hi/lo words [kp][n]
// ===========================================================================
__global__ __launch_bounds__(256) void convert_w(
    const float* __restrict__ W1, const float* __restrict__ W2)
{
    int idx = blockIdx.x * 256 + threadIdx.x;
    if (idx < 128 * 256) {
        int kp = idx >> 8, n = idx & 255;
        uint32_t hi, lo;
        pack2(W1[(2 * kp) * 256 + n], W1[(2 * kp + 1) * 256 + n], hi, lo);
        g_w1hi[idx] = hi; g_w1lo[idx] = lo;
    } else {
        int j = idx - 128 * 256;
        if (j < 128 * 128) {
            int kp = j >> 7, n = j & 127;
            uint32_t hi, lo;
            pack2(W2[(2 * kp) * 128 + n], W2[(2 * kp + 1) * 128 + n], hi, lo);
            g_w2hi[j] = hi; g_w2lo[j] = lo;
        }
    }
}

// ===========================================================================
// Fused MLP: logits[128 rows] = (relu(H@W1+b1))@W2 + b2, one CTA per 128 rows.
// Phase A: h[:,0:128]; Phase B: h[:,128:256] -> packed hi/lo bf16 in SMEM.
// Phase C: GEMM2 from SMEM h. 256 threads, 8 warps (2m x 4n), warp tile 64x32.
// ===========================================================================
__global__ __launch_bounds__(256, 1)
void fused_mlp(const float* __restrict__ H,
               const float* __restrict__ b1, const float* __restrict__ b2,
               float* __restrict__ logits, int M)
{
    extern __shared__ float smem[];
    uint32_t* smw = reinterpret_cast<uint32_t*>(smem);
    const uint32_t smem32 = (uint32_t)__cvta_generic_to_shared(smem);

    const int tid  = threadIdx.x;
    const int lane = tid & 31;
    const int wid  = tid >> 5;
    const int wm   = wid & 1;
    const int wn   = wid >> 1;
    const int gid  = lane >> 2;
    const int tig  = lane & 3;
    const int m0   = blockIdx.x * 128;

    smem[B1_OFF + tid] = b1[tid];
    if (tid < CC) smem[B2_OFF + tid] = b2[tid];

    float acc[4][4][4];

    auto zero_acc = [&]() {
#pragma unroll
        for (int mt = 0; mt < 4; mt++)
#pragma unroll
            for (int nt = 0; nt < 4; nt++)
#pragma unroll
                for (int i = 0; i < 4; i++) acc[mt][nt][i] = 0.f;
    };

    auto issue_A = [&](int c, int stg) {
#pragma unroll
        for (int l = 0; l < 4; l++) {
            int o = tid + 256 * l;
            int row = o >> 3, seg = o & 7;
            int grow = m0 + row;
            int ok = (grow < M);
            cpa16(smem32 + (uint32_t)(SA_OFF(stg) + row * PA + seg * 4) * 4u,
                  &H[(size_t)(ok ? grow : 0) * DD + c * 32 + seg * 4], ok ? 16 : 0);
        }
    };
    auto issue_B = [&](int c, int stg, const uint32_t* Bhi, const uint32_t* Blo,
                       int stride, int ncol0) {
#pragma unroll
        for (int l = 0; l < 2; l++) {
            int o = tid + 256 * l;
            int row = o >> 5, seg = o & 31;
            cpa16(smem32 + (uint32_t)(SBH_OFF(stg) + row * PBW + seg * 4) * 4u,
                  &Bhi[(size_t)(c * 16 + row) * stride + ncol0 + seg * 4], 16);
            cpa16(smem32 + (uint32_t)(SBL_OFF(stg) + row * PBW + seg * 4) * 4u,
                  &Blo[(size_t)(c * 16 + row) * stride + ncol0 + seg * 4], 16);
        }
    };

    auto load_bfrags = [&](int stg, int s, uint32_t bfh[4][2], uint32_t bfl[4][2]) {
        const int kpb = 8 * s + tig;
#pragma unroll
        for (int nt = 0; nt < 4; nt++) {
            int ncol = wn * 32 + nt * 8 + gid;
            bfh[nt][0] = smw[SBH_OFF(stg) + (kpb    ) * PBW + ncol];
            bfh[nt][1] = smw[SBH_OFF(stg) + (kpb + 4) * PBW + ncol];
            bfl[nt][0] = smw[SBL_OFF(stg) + (kpb    ) * PBW + ncol];
            bfl[nt][1] = smw[SBL_OFF(stg) + (kpb + 4) * PBW + ncol];
        }
    };

    // ================= Phases A & B: layer 1 halves =================
#pragma unroll 1
    for (int ph = 0; ph < 2; ph++) {
        const int n0sel = ph * 128;
        zero_acc();
        issue_A(0, 0);
        issue_B(0, 0, g_w1hi, g_w1lo, 256, n0sel);
        CP_COMMIT();

#pragma unroll 1
        for (int c = 0; c < 8; c++) {
            CP_WAIT0();
            __syncthreads();
            if (c < 7) {
                issue_A(c + 1, (c + 1) & 1);
                issue_B(c + 1, (c + 1) & 1, g_w1hi, g_w1lo, 256, n0sel);
                CP_COMMIT();
            }
            const int stg = c & 1;
            const float* sAc = smem + SA_OFF(stg);

#pragma unroll
            for (int s = 0; s < 2; s++) {
                uint32_t bfh[4][2], bfl[4][2];
                load_bfrags(stg, s, bfh, bfl);
#pragma unroll
                for (int mt = 0; mt < 4; mt++) {
                    int mrow = wm * 64 + mt * 16 + gid;
                    int kb = 16 * s + 2 * tig;
                    float2 f0 = *reinterpret_cast<const float2*>(&sAc[(mrow    ) * PA + kb    ]);
                    float2 f1 = *reinterpret_cast<const float2*>(&sAc[(mrow + 8) * PA + kb    ]);
                    float2 f2 = *reinterpret_cast<const float2*>(&sAc[(mrow    ) * PA + kb + 8]);
                    float2 f3 = *reinterpret_cast<const float2*>(&sAc[(mrow + 8) * PA + kb + 8]);
                    uint32_t afh[4], afl[4];
                    pack2(f0.x, f0.y, afh[0], afl[0]);
                    pack2(f1.x, f1.y, afh[1], afl[1]);
                    pack2(f2.x, f2.y, afh[2], afl[2]);
                    pack2(f3.x, f3.y, afh[3], afl[3]);
#pragma unroll
                    for (int nt = 0; nt < 4; nt++)
                        MMA16816(acc[mt][nt], afh, bfh[nt]);
#pragma unroll
                    for (int nt = 0; nt < 4; nt++)
                        MMA16816(acc[mt][nt], afh, bfl[nt]);
#pragma unroll
                    for (int nt = 0; nt < 4; nt++)
                        MMA16816(acc[mt][nt], afl, bfh[nt]);
                }
            }
        }

        // epilogue: relu + pack h -> SMEM (conflict-free: banks 4*gid+tig)
#pragma unroll
        for (int mt = 0; mt < 4; mt++) {
            int rl = wm * 64 + mt * 16 + gid;
#pragma unroll
            for (int nt = 0; nt < 4; nt++) {
                int col = wn * 32 + nt * 8 + 2 * tig;
                float bv0 = smem[B1_OFF + n0sel + col];
                float bv1 = smem[B1_OFF + n0sel + col + 1];
                float x0 = fmaxf(acc[mt][nt][0] + bv0, 0.f);
                float x1 = fmaxf(acc[mt][nt][1] + bv1, 0.f);
                float x2 = fmaxf(acc[mt][nt][2] + bv0, 0.f);
                float x3 = fmaxf(acc[mt][nt][3] + bv1, 0.f);
                int wcol = (n0sel + col) >> 1;
                uint32_t hi, lo;
                pack2(x0, x1, hi, lo);
                smw[HH_OFF + rl * PH + wcol] = hi;
                smw[HL_OFF + rl * PH + wcol] = lo;
                pack2(x2, x3, hi, lo);
                smw[HH_OFF + (rl + 8) * PH + wcol] = hi;
                smw[HL_OFF + (rl + 8) * PH + wcol] = lo;
            }
        }
    }

    // ================= Phase C: layer 2 from SMEM h =================
    zero_acc();
    issue_B(0, 0, g_w2hi, g_w2lo, 128, 0);
    CP_COMMIT();

#pragma unroll 1
    for (int c = 0; c < 8; c++) {
        CP_WAIT0();
        __syncthreads();   // c==0 also orders phase-B h STS before LDS below
        if (c < 7) {
            issue_B(c + 1, (c + 1) & 1, g_w2hi, g_w2lo, 128, 0);
            CP_COMMIT();
        }
        const int stg = c & 1;

#pragma unroll
        for (int s = 0; s < 2; s++) {
            uint32_t bfh[4][2], bfl[4][2];
            load_bfrags(stg, s, bfh, bfl);
            const int kp = c * 16 + 8 * s + tig;
#pragma unroll
            for (int mt = 0; mt < 4; mt++) {
                int rl = wm * 64 + mt * 16 + gid;
                uint32_t afh[4], afl[4];
                afh[0] = smw[HH_OFF + (rl    ) * PH + kp    ];
                afh[1] = smw[HH_OFF + (rl + 8) * PH + kp    ];
                afh[2] = smw[HH_OFF + (rl    ) * PH + kp + 4];
                afh[3] = smw[HH_OFF + (rl + 8) * PH + kp + 4];
                afl[0] = smw[HL_OFF + (rl    ) * PH + kp    ];
                afl[1] = smw[HL_OFF + (rl + 8) * PH + kp    ];
                afl[2] = smw[HL_OFF + (rl    ) * PH + kp + 4];
                afl[3] = smw[HL_OFF + (rl + 8) * PH + kp + 4];
#pragma unroll
                for (int nt = 0; nt < 4; nt++)
                    MMA16816(acc[mt][nt], afh, bfh[nt]);
#pragma unroll
                for (int nt = 0; nt < 4; nt++)
                    MMA16816(acc[mt][nt], afh, bfl[nt]);
#pragma unroll
                for (int nt = 0; nt < 4; nt++)
                    MMA16816(acc[mt][nt], afl, bfh[nt]);
            }
        }
    }

    // epilogue: logits = acc + b2
#pragma unroll
    for (int mt = 0; mt < 4; mt++) {
        int r0 = m0 + wm * 64 + mt * 16 + gid;
#pragma unroll
        for (int nt = 0; nt < 4; nt++) {
            int col = wn * 32 + nt * 8 + 2 * tig;
            float bv0 = smem[B2_OFF + col], bv1 = smem[B2_OFF + col + 1];
            float x0 = acc[mt][nt][0] + bv0;
            float x1 = acc[mt][nt][1] + bv1;
            float x2 = acc[mt][nt][2] + bv0;
            float x3 = acc[mt][nt][3] + bv1;
            if (r0 < M)
                *reinterpret_cast<float2*>(&logits[(size_t)r0 * CC + col]) =
                    make_float2(x0, x1);
            if (r0 + 8 < M)
                *reinterpret_cast<float2*>(&logits[(size_t)(r0 + 8) * CC + col]) =
                    make_float2(x2, x3);
        }
    }
}

// ===========================================================================
// Segment softmax, vectorized: 4 rows in flight (q = tid/32), float4 columns.
// ===========================================================================
__device__ __forceinline__ int lower_bound_i32(const int* __restrict__ a,
                                               int n, int key)
{
    int lo = 0, hi = n;
    while (lo < hi) {
        int mid = (lo + hi) >> 1;
        if (a[mid] < key) lo = mid + 1; else hi = mid;
    }
    return lo;
}

__device__ __forceinline__ void upd(float& m, float& s, float x) {
    if (x > m) { s = s * __expf(m - x) + 1.f; m = x; }
    else       { s += __expf(x - m); }
}

__global__ __launch_bounds__(128) void seg_softmax(
    const float* __restrict__ logits,
    const int* __restrict__ batch,
    float* __restrict__ probs)
{
    __shared__ float sm_m[4 * 128];
    __shared__ float sm_s[4 * 128];

    const int s   = blockIdx.x;
    const int lo  = lower_bound_i32(batch, NN, s);
    const int hi  = lower_bound_i32(batch, NN, s + 1);
    const int q   = threadIdx.x >> 5;          // 0..3: row residue
    const int cb  = (threadIdx.x & 31) * 4;    // column base

    float m[4] = {-CUDART_INF_F, -CUDART_INF_F, -CUDART_INF_F, -CUDART_INF_F};
    float sum[4] = {0.f, 0.f, 0.f, 0.f};

    for (int r = lo + q; r < hi; r += 4) {
        float4 v = *reinterpret_cast<const float4*>(&logits[(size_t)r * CC + cb]);
        upd(m[0], sum[0], v.x);
        upd(m[1], sum[1], v.y);
        upd(m[2], sum[2], v.z);
        upd(m[3], sum[3], v.w);
    }
#pragma unroll
    for (int j = 0; j < 4; j++) {
        sm_m[q * 128 + cb + j] = m[j];
        sm_s[q * 128 + cb + j] = sum[j];
    }
    __syncthreads();

    // combine 4 partials for column c
    const int c = threadIdx.x;
    float M = -CUDART_INF_F, S = 0.f;
#pragma unroll
    for (int qq = 0; qq < 4; qq++) {
        float mq = sm_m[qq * 128 + c], sq = sm_s[qq * 128 + c];
        if (sq > 0.f) {
            float nm = fmaxf(M, mq);
            S = S * __expf(M - nm) + sq * __expf(mq - nm);
            M = nm;
        }
    }
    __syncthreads();
    sm_m[c] = M;
    sm_s[c] = (S > 0.f) ? (1.f / S) : 0.f;
    __syncthreads();

    float mm[4], ii[4];
#pragma unroll
    for (int j = 0; j < 4; j++) { mm[j] = sm_m[cb + j]; ii[j] = sm_s[cb + j]; }

    for (int r = lo + q; r < hi; r += 4) {
        float4 v = *reinterpret_cast<const float4*>(&logits[(size_t)r * CC + cb]);
        float4 o;
        o.x = __expf(v.x - mm[0]) * ii[0];
        o.y = __expf(v.y - mm[1]) * ii[1];
        o.z = __expf(v.z - mm[2]) * ii[2];
        o.w = __expf(v.w - mm[3]) * ii[3];
        *reinterpret_cast<float4*>(&probs[(size_t)r * CC + cb]) = o;
    }
}

// ===========================================================================
// Launch
// ===========================================================================
extern "C" void kernel_launch(void* const* d_in, const int* in_sizes, int n_in,
                              void* d_out, int out_size)
{
    const float* H  = nullptr;
    const int*   batch = nullptr;
    const float* W1 = nullptr;
    const float* b1 = nullptr;
    const float* W2 = nullptr;
    const float* b2 = nullptr;

    for (int i = 0; i < n_in; i++) {
        switch (in_sizes[i]) {
            case 128000000: H     = (const float*)d_in[i]; break;
            case 500000:    batch = (const int*)d_in[i];   break;
            case 65536:     W1    = (const float*)d_in[i]; break;
            case 256:       b1    = (const float*)d_in[i]; break;
            case 32768:     W2    = (const float*)d_in[i]; break;
            case 128:       b2    = (const float*)d_in[i]; break;
            default: break;
        }
    }

    float* out    = (float*)d_out;
    float* logits = out;
    float* probs  = out + (size_t)NN * CC;

    cudaFuncSetAttribute(fused_mlp,
                         cudaFuncAttributeMaxDynamicSharedMemorySize, SMEM_BYTES);

    convert_w<<<192, 256>>>(W1, W2);

    const int mblocks = (NN + 127) / 128;      // 3907
    fused_mlp<<<mblocks, 256, SMEM_BYTES>>>(H, b1, b2, logits, NN);

    seg_softmax<<<SSEG, 128>>>(logits, batch, probs);
}

// round 10
// speedup vs baseline: 3.2557x; 1.3663x over previous
#include <cuda_runtime.h>
#include <cuda_fp16.h>
#include <math_constants.h>
#include <cstdint>

#define NN 500000
#define DD 256
#define CC 128
#define SSEG 2048

#define BM 128
#define BN 128
#define BK 32
#define PA  40    // A fp32 stage pitch (floats): %32==8 -> conflict-free LDS.64
#define PAW 20    // A fp16-word pitch: banks (gid*20+tig)%32 all distinct
#define PBW 136   // B word pitch: banks (tig*8+gid)%32 all distinct

// smem word offsets (19200 words = 76800 B; 2 CTAs/SM)
#define SA_OFF(s)   ((s) * 5120)            // gemm1: A fp32 128*40, 2 stages
#define SAH_OFF(s)  ((s) * 2560)            // gemm2: A fp16 words 128*20
#define SBH_OFF(s)  (10240 + (s) * 2176)    // B hi: 16*136
#define SBL_OFF(s)  (14592 + (s) * 2176)    // B lo
#define BIAS_OFF    18944
#define SMEM_BYTES  (19200 * 4)

// h stored as single fp16x2 words [m][kp]: 256 MB.
__device__ uint32_t g_h16[(long long)NN * 128];
// pre-split weights (fp16 hi/lo), word layout [kp][n]
__device__ uint32_t g_w1hi[128 * 256], g_w1lo[128 * 256];
__device__ uint32_t g_w2hi[128 * 128], g_w2lo[128 * 128];

#define MMA16816F16(d, a, b)                                                  \
    asm volatile(                                                             \
        "mma.sync.aligned.m16n8k16.row.col.f32.f16.f16.f32 "                  \
        "{%0,%1,%2,%3}, {%4,%5,%6,%7}, {%8,%9}, {%0,%1,%2,%3};"               \
        : "+f"((d)[0]), "+f"((d)[1]), "+f"((d)[2]), "+f"((d)[3])              \
        : "r"((a)[0]), "r"((a)[1]), "r"((a)[2]), "r"((a)[3]),                 \
          "r"((b)[0]), "r"((b)[1]))

__device__ __forceinline__ uint32_t pack1h(float x, float y) {
    __half2 h = __floats2half2_rn(x, y);
    return *reinterpret_cast<uint32_t*>(&h);
}
__device__ __forceinline__ void pack2h(float x, float y, uint32_t& hi, uint32_t& lo) {
    __half2 h = __floats2half2_rn(x, y);
    hi = *reinterpret_cast<uint32_t*>(&h);
    float rx = x - __low2float(h);
    float ry = y - __high2float(h);
    __half2 l = __floats2half2_rn(rx, ry);
    lo = *reinterpret_cast<uint32_t*>(&l);
}

__device__ __forceinline__ void cpa16(uint32_t dst, const void* src, int srcsz) {
    asm volatile("cp.async.cg.shared.global [%0], [%1], 16, %2;"
                 :: "r"(dst), "l"(src), "r"(srcsz));
}
#define CP_COMMIT()  asm volatile("cp.async.commit_group;" ::: "memory")
#define CP_WAIT0()   asm volatile("cp.async.wait_group 0;" ::: "memory")

// ===========================================================================
// Weight pre-split: W[k][n] fp32 -> fp16 hi/lo words [kp][n]
// ===========================================================================
__global__ __launch_bounds__(256) void convert_w(
    const float* __restrict__ W1, const float* __restrict__ W2)
{
    int idx = blockIdx.x * 256 + threadIdx.x;
    if (idx < 128 * 256) {
        int kp = idx >> 8, n = idx & 255;
        uint32_t hi, lo;
        pack2h(W1[(2 * kp) * 256 + n], W1[(2 * kp + 1) * 256 + n], hi, lo);
        g_w1hi[idx] = hi; g_w1lo[idx] = lo;
    } else {
        int j = idx - 128 * 256;
        if (j < 128 * 128) {
            int kp = j >> 7, n = j & 127;
            uint32_t hi, lo;
            pack2h(W2[(2 * kp) * 128 + n], W2[(2 * kp + 1) * 128 + n], hi, lo);
            g_w2hi[j] = hi; g_w2lo[j] = lo;
        }
    }
}

// ===========================================================================
// HMMA fp16 2-product GEMM: Cout = act(A @ W + bias), W pre-split hi/lo fp16,
// A single fp16 (AFP16: pre-converted words; else fp32 converted at frag load).
// WH16: write output as packed fp16 words (h) vs fp32 (logits).
// CTA 128x128, 8 warps (2m x 4n), warp tile 64x32, BK=32, 2-stage cp.async.
// ===========================================================================
template <int AFP16, int WH16>
__global__ __launch_bounds__(256, 2)
void gemm_hmma(const float* __restrict__ A32,
               const uint32_t* __restrict__ A16,
               const uint32_t* __restrict__ Bhi, const uint32_t* __restrict__ Blo,
               const float* __restrict__ bias,
               float* __restrict__ Cout, uint32_t* __restrict__ C16,
               int M, int Nfull, int relu)
{
    extern __shared__ float smem[];
    uint32_t* smw = reinterpret_cast<uint32_t*>(smem);
    const uint32_t smem32 = (uint32_t)__cvta_generic_to_shared(smem);

    const int tid  = threadIdx.x;
    const int lane = tid & 31;
    const int wid  = tid >> 5;
    const int wm   = wid & 1;
    const int wn   = wid >> 1;
    const int gid  = lane >> 2;
    const int tig  = lane & 3;
    const int m0   = blockIdx.x * BM;
    const int n0   = blockIdx.y * BN;

    if (tid < BN) smem[BIAS_OFF + tid] = bias[n0 + tid];

    float acc[4][4][4];
#pragma unroll
    for (int mt = 0; mt < 4; mt++)
#pragma unroll
        for (int nt = 0; nt < 4; nt++)
#pragma unroll
            for (int i = 0; i < 4; i++) acc[mt][nt][i] = 0.f;

    auto issue_chunk = [&](int c, int stg) {
        if (AFP16) {
            // A: fp16 words [m][128]; chunk = 128 rows x 16 words
#pragma unroll
            for (int l = 0; l < 2; l++) {
                int o = tid + 256 * l;
                int row = o >> 2, seg = o & 3;
                int grow = m0 + row;
                int ok = (grow < M);
                cpa16(smem32 + (uint32_t)(SAH_OFF(stg) + row * PAW + seg * 4) * 4u,
                      &A16[(size_t)(ok ? grow : 0) * 128 + c * 16 + seg * 4], ok ? 16 : 0);
            }
        } else {
            // A: fp32 [m][256]; chunk = 128 rows x 32 floats
#pragma unroll
            for (int l = 0; l < 4; l++) {
                int o = tid + 256 * l;
                int row = o >> 3, seg = o & 7;
                int grow = m0 + row;
                int ok = (grow < M);
                cpa16(smem32 + (uint32_t)(SA_OFF(stg) + row * PA + seg * 4) * 4u,
                      &A32[(size_t)(ok ? grow : 0) * DD + c * BK + seg * 4], ok ? 16 : 0);
            }
        }
        // B: hi/lo words [kp][Nfull]; chunk = 16 rows x 128 cols
#pragma unroll
        for (int l = 0; l < 2; l++) {
            int o = tid + 256 * l;
            int row = o >> 5, seg = o & 31;
            cpa16(smem32 + (uint32_t)(SBH_OFF(stg) + row * PBW + seg * 4) * 4u,
                  &Bhi[(size_t)(c * 16 + row) * Nfull + n0 + seg * 4], 16);
            cpa16(smem32 + (uint32_t)(SBL_OFF(stg) + row * PBW + seg * 4) * 4u,
                  &Blo[(size_t)(c * 16 + row) * Nfull + n0 + seg * 4], 16);
        }
        CP_COMMIT();
    };

    issue_chunk(0, 0);

#pragma unroll 1
    for (int c = 0; c < 8; c++) {
        CP_WAIT0();
        __syncthreads();
        if (c < 7) issue_chunk(c + 1, (c + 1) & 1);

        const int stg = c & 1;

#pragma unroll
        for (int s = 0; s < 2; s++) {
            // ---- B fragments hi/lo ----
            uint32_t bfh[4][2], bfl[4][2];
            const int kpb = 8 * s + tig;
#pragma unroll
            for (int nt = 0; nt < 4; nt++) {
                int ncol = wn * 32 + nt * 8 + gid;
                bfh[nt][0] = smw[SBH_OFF(stg) + (kpb    ) * PBW + ncol];
                bfh[nt][1] = smw[SBH_OFF(stg) + (kpb + 4) * PBW + ncol];
                bfl[nt][0] = smw[SBL_OFF(stg) + (kpb    ) * PBW + ncol];
                bfl[nt][1] = smw[SBL_OFF(stg) + (kpb + 4) * PBW + ncol];
            }
            // ---- A fragments (single fp16) for all mt ----
            uint32_t af[4][4];
#pragma unroll
            for (int mt = 0; mt < 4; mt++) {
                int mrow = wm * 64 + mt * 16 + gid;
                if (AFP16) {
                    const int kpa = 8 * s + tig;
                    af[mt][0] = smw[SAH_OFF(stg) + (mrow    ) * PAW + kpa    ];
                    af[mt][1] = smw[SAH_OFF(stg) + (mrow + 8) * PAW + kpa    ];
                    af[mt][2] = smw[SAH_OFF(stg) + (mrow    ) * PAW + kpa + 4];
                    af[mt][3] = smw[SAH_OFF(stg) + (mrow + 8) * PAW + kpa + 4];
                } else {
                    const float* sAc = smem + SA_OFF(stg);
                    int kb = 16 * s + 2 * tig;
                    float2 f0 = *reinterpret_cast<const float2*>(&sAc[(mrow    ) * PA + kb    ]);
                    float2 f1 = *reinterpret_cast<const float2*>(&sAc[(mrow + 8) * PA + kb    ]);
                    float2 f2 = *reinterpret_cast<const float2*>(&sAc[(mrow    ) * PA + kb + 8]);
                    float2 f3 = *reinterpret_cast<const float2*>(&sAc[(mrow + 8) * PA + kb + 8]);
                    af[mt][0] = pack1h(f0.x, f0.y);
                    af[mt][1] = pack1h(f1.x, f1.y);
                    af[mt][2] = pack1h(f2.x, f2.y);
                    af[mt][3] = pack1h(f3.x, f3.y);
                }
            }
            // ---- 2 products, product-outer (same-acc reuse distance 16) ----
#pragma unroll
            for (int mt = 0; mt < 4; mt++)
#pragma unroll
                for (int nt = 0; nt < 4; nt++)
                    MMA16816F16(acc[mt][nt], af[mt], bfh[nt]);
#pragma unroll
            for (int mt = 0; mt < 4; mt++)
#pragma unroll
                for (int nt = 0; nt < 4; nt++)
                    MMA16816F16(acc[mt][nt], af[mt], bfl[nt]);
        }
    }

    // ---- epilogue ----
    const float* sbias = smem + BIAS_OFF;
#pragma unroll
    for (int mt = 0; mt < 4; mt++) {
        int r0 = m0 + wm * 64 + mt * 16 + gid;
#pragma unroll
        for (int nt = 0; nt < 4; nt++) {
            int col = wn * 32 + nt * 8 + 2 * tig;
            float bv0 = sbias[col], bv1 = sbias[col + 1];
            float x0 = acc[mt][nt][0] + bv0;
            float x1 = acc[mt][nt][1] + bv1;
            float x2 = acc[mt][nt][2] + bv0;
            float x3 = acc[mt][nt][3] + bv1;
            if (relu) {
                x0 = fmaxf(x0, 0.f); x1 = fmaxf(x1, 0.f);
                x2 = fmaxf(x2, 0.f); x3 = fmaxf(x3, 0.f);
            }
            if (WH16) {
                int wcol = (n0 + col) >> 1;
                if (r0 < M)
                    C16[(size_t)r0 * 128 + wcol] = pack1h(x0, x1);
                if (r0 + 8 < M)
                    C16[(size_t)(r0 + 8) * 128 + wcol] = pack1h(x2, x3);
            } else {
                if (r0 < M)
                    *reinterpret_cast<float2*>(&Cout[(size_t)r0 * Nfull + n0 + col]) =
                        make_float2(x0, x1);
                if (r0 + 8 < M)
                    *reinterpret_cast<float2*>(&Cout[(size_t)(r0 + 8) * Nfull + n0 + col]) =
                        make_float2(x2, x3);
            }
        }
    }
}

// ===========================================================================
// Segment softmax, vectorized: 4 rows in flight (q = tid/32), float4 columns.
// ===========================================================================
__device__ __forceinline__ int lower_bound_i32(const int* __restrict__ a,
                                               int n, int key)
{
    int lo = 0, hi = n;
    while (lo < hi) {
        int mid = (lo + hi) >> 1;
        if (a[mid] < key) lo = mid + 1; else hi = mid;
    }
    return lo;
}

__device__ __forceinline__ void upd(float& m, float& s, float x) {
    if (x > m) { s = s * __expf(m - x) + 1.f; m = x; }
    else       { s += __expf(x - m); }
}

__global__ __launch_bounds__(128) void seg_softmax(
    const float* __restrict__ logits,
    const int* __restrict__ batch,
    float* __restrict__ probs)
{
    __shared__ float sm_m[4 * 128];
    __shared__ float sm_s[4 * 128];

    const int s   = blockIdx.x;
    const int lo  = lower_bound_i32(batch, NN, s);
    const int hi  = lower_bound_i32(batch, NN, s + 1);
    const int q   = threadIdx.x >> 5;
    const int cb  = (threadIdx.x & 31) * 4;

    float m[4] = {-CUDART_INF_F, -CUDART_INF_F, -CUDART_INF_F, -CUDART_INF_F};
    float sum[4] = {0.f, 0.f, 0.f, 0.f};

    for (int r = lo + q; r < hi; r += 4) {
        float4 v = *reinterpret_cast<const float4*>(&logits[(size_t)r * CC + cb]);
        upd(m[0], sum[0], v.x);
        upd(m[1], sum[1], v.y);
        upd(m[2], sum[2], v.z);
        upd(m[3], sum[3], v.w);
    }
#pragma unroll
    for (int j = 0; j < 4; j++) {
        sm_m[q * 128 + cb + j] = m[j];
        sm_s[q * 128 + cb + j] = sum[j];
    }
    __syncthreads();

    const int c = threadIdx.x;
    float M = -CUDART_INF_F, S = 0.f;
#pragma unroll
    for (int qq = 0; qq < 4; qq++) {
        float mq = sm_m[qq * 128 + c], sq = sm_s[qq * 128 + c];
        if (sq > 0.f) {
            float nm = fmaxf(M, mq);
            S = S * __expf(M - nm) + sq * __expf(mq - nm);
            M = nm;
        }
    }
    __syncthreads();
    sm_m[c] = M;
    sm_s[c] = (S > 0.f) ? (1.f / S) : 0.f;
    __syncthreads();

    float mm[4], ii[4];
#pragma unroll
    for (int j = 0; j < 4; j++) { mm[j] = sm_m[cb + j]; ii[j] = sm_s[cb + j]; }

    for (int r = lo + q; r < hi; r += 4) {
        float4 v = *reinterpret_cast<const float4*>(&logits[(size_t)r * CC + cb]);
        float4 o;
        o.x = __expf(v.x - mm[0]) * ii[0];
        o.y = __expf(v.y - mm[1]) * ii[1];
        o.z = __expf(v.z - mm[2]) * ii[2];
        o.w = __expf(v.w - mm[3]) * ii[3];
        *reinterpret_cast<float4*>(&probs[(size_t)r * CC + cb]) = o;
    }
}

// ===========================================================================
// Launch
// ===========================================================================
extern "C" void kernel_launch(void* const* d_in, const int* in_sizes, int n_in,
                              void* d_out, int out_size)
{
    const float* H  = nullptr;
    const int*   batch = nullptr;
    const float* W1 = nullptr;
    const float* b1 = nullptr;
    const float* W2 = nullptr;
    const float* b2 = nullptr;

    for (int i = 0; i < n_in; i++) {
        switch (in_sizes[i]) {
            case 128000000: H     = (const float*)d_in[i]; break;
            case 500000:    batch = (const int*)d_in[i];   break;
            case 65536:     W1    = (const float*)d_in[i]; break;
            case 256:       b1    = (const float*)d_in[i]; break;
            case 32768:     W2    = (const float*)d_in[i]; break;
            case 128:       b2    = (const float*)d_in[i]; break;
            default: break;
        }
    }

    float* out    = (float*)d_out;
    float* logits = out;
    float* probs  = out + (size_t)NN * CC;

    void *h16, *w1hi, *w1lo, *w2hi, *w2lo;
    cudaGetSymbolAddress(&h16, g_h16);
    cudaGetSymbolAddress(&w1hi, g_w1hi);
    cudaGetSymbolAddress(&w1lo, g_w1lo);
    cudaGetSymbolAddress(&w2hi, g_w2hi);
    cudaGetSymbolAddress(&w2lo, g_w2lo);

    cudaFuncSetAttribute(gemm_hmma<0, 1>,
                         cudaFuncAttributeMaxDynamicSharedMemorySize, SMEM_BYTES);
    cudaFuncSetAttribute(gemm_hmma<1, 0>,
                         cudaFuncAttributeMaxDynamicSharedMemorySize, SMEM_BYTES);

    convert_w<<<192, 256>>>(W1, W2);

    const int mblocks = (NN + BM - 1) / BM;    // 3907

    // Layer 1: h = relu(H @ W1 + b1), written as packed fp16 words
    dim3 g1(mblocks, DD / BN);                 // 3907 x 2
    gemm_hmma<0, 1><<<g1, 256, SMEM_BYTES>>>(
        H, nullptr, (const uint32_t*)w1hi, (const uint32_t*)w1lo,
        b1, nullptr, (uint32_t*)h16, NN, DD, 1);

    // Layer 2: logits = h @ W2 + b2 (fp32 out)
    dim3 g2(mblocks, CC / BN);                 // 3907 x 1
    gemm_hmma<1, 0><<<g2, 256, SMEM_BYTES>>>(
        nullptr, (const uint32_t*)h16, (const uint32_t*)w2hi, (const uint32_t*)w2lo,
        b2, logits, nullptr, NN, CC, 0);

    // Segment softmax -> probs
    seg_softmax<<<SSEG, 128>>>(logits, batch, probs);
}

// round 11
// speedup vs baseline: 3.7404x; 1.1489x over previous
#include <cuda_runtime.h>
#include <cuda_fp16.h>
#include <math_constants.h>
#include <cstdint>

#define NN 500000
#define DD 256
#define CC 128
#define SSEG 2048

#define BM 128
#define BN 128
#define BK 32
#define PA  40    // A fp32 stage pitch (floats): %32==8 -> conflict-free LDS.64
#define PAW 20    // A fp16-word pitch: banks (gid*20+tig)%32 all distinct
#define PBW 136   // B word pitch: banks (tig*8+gid)%32 all distinct

// smem word offsets (19200 words = 76800 B; 2 CTAs/SM)
#define SA_OFF(s)   ((s) * 5120)            // gemm1: A fp32 128*40, 2 stages
#define SAH_OFF(s)  ((s) * 2560)            // gemm2: A fp16 words 128*20
#define SBH_OFF(s)  (10240 + (s) * 2176)    // B hi: 16*136
#define SBL_OFF(s)  (14592 + (s) * 2176)    // B lo
#define BIAS_OFF    18944
#define SMEM_BYTES  (19200 * 4)

// h stored as single fp16x2 words [m][kp]: 256 MB.
__device__ uint32_t g_h16[(long long)NN * 128];
// pre-split weights (fp16 hi/lo), word layout [kp][n]
__device__ uint32_t g_w1hi[128 * 256], g_w1lo[128 * 256];
__device__ uint32_t g_w2hi[128 * 128], g_w2lo[128 * 128];

#define MMA16816F16(d, a, b)                                                  \
    asm volatile(                                                             \
        "mma.sync.aligned.m16n8k16.row.col.f32.f16.f16.f32 "                  \
        "{%0,%1,%2,%3}, {%4,%5,%6,%7}, {%8,%9}, {%0,%1,%2,%3};"               \
        : "+f"((d)[0]), "+f"((d)[1]), "+f"((d)[2]), "+f"((d)[3])              \
        : "r"((a)[0]), "r"((a)[1]), "r"((a)[2]), "r"((a)[3]),                 \
          "r"((b)[0]), "r"((b)[1]))

__device__ __forceinline__ uint32_t pack1h(float x, float y) {
    __half2 h = __floats2half2_rn(x, y);
    return *reinterpret_cast<uint32_t*>(&h);
}
__device__ __forceinline__ void pack2h(float x, float y, uint32_t& hi, uint32_t& lo) {
    __half2 h = __floats2half2_rn(x, y);
    hi = *reinterpret_cast<uint32_t*>(&h);
    float rx = x - __low2float(h);
    float ry = y - __high2float(h);
    __half2 l = __floats2half2_rn(rx, ry);
    lo = *reinterpret_cast<uint32_t*>(&l);
}

__device__ __forceinline__ void cpa16(uint32_t dst, const void* src, int srcsz) {
    asm volatile("cp.async.cg.shared.global [%0], [%1], 16, %2;"
                 :: "r"(dst), "l"(src), "r"(srcsz));
}
#define CP_COMMIT()  asm volatile("cp.async.commit_group;" ::: "memory")
#define CP_WAIT0()   asm volatile("cp.async.wait_group 0;" ::: "memory")

// ===========================================================================
// Weight pre-split: W[k][n] fp32 -> fp16 hi/lo words [kp][n]
// ===========================================================================
__global__ __launch_bounds__(256) void convert_w(
    const float* __restrict__ W1, const float* __restrict__ W2)
{
    int idx = blockIdx.x * 256 + threadIdx.x;
    if (idx < 128 * 256) {
        int kp = idx >> 8, n = idx & 255;
        uint32_t hi, lo;
        pack2h(W1[(2 * kp) * 256 + n], W1[(2 * kp + 1) * 256 + n], hi, lo);
        g_w1hi[idx] = hi; g_w1lo[idx] = lo;
    } else {
        int j = idx - 128 * 256;
        if (j < 128 * 128) {
            int kp = j >> 7, n = j & 127;
            uint32_t hi, lo;
            pack2h(W2[(2 * kp) * 128 + n], W2[(2 * kp + 1) * 128 + n], hi, lo);
            g_w2hi[j] = hi; g_w2lo[j] = lo;
        }
    }
}

// ===========================================================================
// HMMA fp16 GEMM: Cout = act(A @ W + bias).
// AFP16: A pre-converted fp16 words vs fp32 (converted at frag load).
// WH16:  write packed fp16 words (h) vs fp32 (logits).
// BSPLIT: B = hi+lo 2-product vs hi-only single product.
// CTA 128x128, 8 warps (2m x 4n), warp tile 64x32, BK=32, 2-stage cp.async.
// ===========================================================================
template <int AFP16, int WH16, int BSPLIT>
__global__ __launch_bounds__(256, 2)
void gemm_hmma(const float* __restrict__ A32,
               const uint32_t* __restrict__ A16,
               const uint32_t* __restrict__ Bhi, const uint32_t* __restrict__ Blo,
               const float* __restrict__ bias,
               float* __restrict__ Cout, uint32_t* __restrict__ C16,
               int M, int Nfull, int relu)
{
    extern __shared__ float smem[];
    uint32_t* smw = reinterpret_cast<uint32_t*>(smem);
    const uint32_t smem32 = (uint32_t)__cvta_generic_to_shared(smem);

    const int tid  = threadIdx.x;
    const int lane = tid & 31;
    const int wid  = tid >> 5;
    const int wm   = wid & 1;
    const int wn   = wid >> 1;
    const int gid  = lane >> 2;
    const int tig  = lane & 3;
    const int m0   = blockIdx.x * BM;
    const int n0   = blockIdx.y * BN;

    if (tid < BN) smem[BIAS_OFF + tid] = bias[n0 + tid];

    float acc[4][4][4];
#pragma unroll
    for (int mt = 0; mt < 4; mt++)
#pragma unroll
        for (int nt = 0; nt < 4; nt++)
#pragma unroll
            for (int i = 0; i < 4; i++) acc[mt][nt][i] = 0.f;

    auto issue_chunk = [&](int c, int stg) {
        if (AFP16) {
#pragma unroll
            for (int l = 0; l < 2; l++) {
                int o = tid + 256 * l;
                int row = o >> 2, seg = o & 3;
                int grow = m0 + row;
                int ok = (grow < M);
                cpa16(smem32 + (uint32_t)(SAH_OFF(stg) + row * PAW + seg * 4) * 4u,
                      &A16[(size_t)(ok ? grow : 0) * 128 + c * 16 + seg * 4], ok ? 16 : 0);
            }
        } else {
#pragma unroll
            for (int l = 0; l < 4; l++) {
                int o = tid + 256 * l;
                int row = o >> 3, seg = o & 7;
                int grow = m0 + row;
                int ok = (grow < M);
                cpa16(smem32 + (uint32_t)(SA_OFF(stg) + row * PA + seg * 4) * 4u,
                      &A32[(size_t)(ok ? grow : 0) * DD + c * BK + seg * 4], ok ? 16 : 0);
            }
        }
#pragma unroll
        for (int l = 0; l < 2; l++) {
            int o = tid + 256 * l;
            int row = o >> 5, seg = o & 31;
            cpa16(smem32 + (uint32_t)(SBH_OFF(stg) + row * PBW + seg * 4) * 4u,
                  &Bhi[(size_t)(c * 16 + row) * Nfull + n0 + seg * 4], 16);
            if (BSPLIT)
                cpa16(smem32 + (uint32_t)(SBL_OFF(stg) + row * PBW + seg * 4) * 4u,
                      &Blo[(size_t)(c * 16 + row) * Nfull + n0 + seg * 4], 16);
        }
        CP_COMMIT();
    };

    issue_chunk(0, 0);

#pragma unroll 1
    for (int c = 0; c < 8; c++) {
        CP_WAIT0();
        __syncthreads();
        if (c < 7) issue_chunk(c + 1, (c + 1) & 1);

        const int stg = c & 1;

#pragma unroll
        for (int s = 0; s < 2; s++) {
            // ---- B fragments ----
            uint32_t bfh[4][2], bfl[4][2];
            const int kpb = 8 * s + tig;
#pragma unroll
            for (int nt = 0; nt < 4; nt++) {
                int ncol = wn * 32 + nt * 8 + gid;
                bfh[nt][0] = smw[SBH_OFF(stg) + (kpb    ) * PBW + ncol];
                bfh[nt][1] = smw[SBH_OFF(stg) + (kpb + 4) * PBW + ncol];
                if (BSPLIT) {
                    bfl[nt][0] = smw[SBL_OFF(stg) + (kpb    ) * PBW + ncol];
                    bfl[nt][1] = smw[SBL_OFF(stg) + (kpb + 4) * PBW + ncol];
                }
            }
            // ---- A fragments (single fp16) ----
            uint32_t af[4][4];
#pragma unroll
            for (int mt = 0; mt < 4; mt++) {
                int mrow = wm * 64 + mt * 16 + gid;
                if (AFP16) {
                    const int kpa = 8 * s + tig;
                    af[mt][0] = smw[SAH_OFF(stg) + (mrow    ) * PAW + kpa    ];
                    af[mt][1] = smw[SAH_OFF(stg) + (mrow + 8) * PAW + kpa    ];
                    af[mt][2] = smw[SAH_OFF(stg) + (mrow    ) * PAW + kpa + 4];
                    af[mt][3] = smw[SAH_OFF(stg) + (mrow + 8) * PAW + kpa + 4];
                } else {
                    const float* sAc = smem + SA_OFF(stg);
                    int kb = 16 * s + 2 * tig;
                    float2 f0 = *reinterpret_cast<const float2*>(&sAc[(mrow    ) * PA + kb    ]);
                    float2 f1 = *reinterpret_cast<const float2*>(&sAc[(mrow + 8) * PA + kb    ]);
                    float2 f2 = *reinterpret_cast<const float2*>(&sAc[(mrow    ) * PA + kb + 8]);
                    float2 f3 = *reinterpret_cast<const float2*>(&sAc[(mrow + 8) * PA + kb + 8]);
                    af[mt][0] = pack1h(f0.x, f0.y);
                    af[mt][1] = pack1h(f1.x, f1.y);
                    af[mt][2] = pack1h(f2.x, f2.y);
                    af[mt][3] = pack1h(f3.x, f3.y);
                }
            }
#pragma unroll
            for (int mt = 0; mt < 4; mt++)
#pragma unroll
                for (int nt = 0; nt < 4; nt++)
                    MMA16816F16(acc[mt][nt], af[mt], bfh[nt]);
            if (BSPLIT) {
#pragma unroll
                for (int mt = 0; mt < 4; mt++)
#pragma unroll
                    for (int nt = 0; nt < 4; nt++)
                        MMA16816F16(acc[mt][nt], af[mt], bfl[nt]);
            }
        }
    }

    // ---- epilogue ----
    const float* sbias = smem + BIAS_OFF;
#pragma unroll
    for (int mt = 0; mt < 4; mt++) {
        int r0 = m0 + wm * 64 + mt * 16 + gid;
#pragma unroll
        for (int nt = 0; nt < 4; nt++) {
            int col = wn * 32 + nt * 8 + 2 * tig;
            float bv0 = sbias[col], bv1 = sbias[col + 1];
            float x0 = acc[mt][nt][0] + bv0;
            float x1 = acc[mt][nt][1] + bv1;
            float x2 = acc[mt][nt][2] + bv0;
            float x3 = acc[mt][nt][3] + bv1;
            if (relu) {
                x0 = fmaxf(x0, 0.f); x1 = fmaxf(x1, 0.f);
                x2 = fmaxf(x2, 0.f); x3 = fmaxf(x3, 0.f);
            }
            if (WH16) {
                int wcol = (n0 + col) >> 1;
                if (r0 < M)
                    C16[(size_t)r0 * 128 + wcol] = pack1h(x0, x1);
                if (r0 + 8 < M)
                    C16[(size_t)(r0 + 8) * 128 + wcol] = pack1h(x2, x3);
            } else {
                if (r0 < M)
                    *reinterpret_cast<float2*>(&Cout[(size_t)r0 * Nfull + n0 + col]) =
                        make_float2(x0, x1);
                if (r0 + 8 < M)
                    *reinterpret_cast<float2*>(&Cout[(size_t)(r0 + 8) * Nfull + n0 + col]) =
                        make_float2(x2, x3);
            }
        }
    }
}

// ===========================================================================
// Segment softmax: 256 threads, 8 rows in flight (q = tid/32), float4 cols.
// ===========================================================================
__device__ __forceinline__ int lower_bound_i32(const int* __restrict__ a,
                                               int n, int key)
{
    int lo = 0, hi = n;
    while (lo < hi) {
        int mid = (lo + hi) >> 1;
        if (a[mid] < key) lo = mid + 1; else hi = mid;
    }
    return lo;
}

__device__ __forceinline__ void upd(float& m, float& s, float x) {
    if (x > m) { s = s * __expf(m - x) + 1.f; m = x; }
    else       { s += __expf(x - m); }
}

__global__ __launch_bounds__(256) void seg_softmax(
    const float* __restrict__ logits,
    const int* __restrict__ batch,
    float* __restrict__ probs)
{
    __shared__ float sm_m[8 * 128];
    __shared__ float sm_s[8 * 128];

    const int s   = blockIdx.x;
    const int lo  = lower_bound_i32(batch, NN, s);
    const int hi  = lower_bound_i32(batch, NN, s + 1);
    const int q   = threadIdx.x >> 5;          // 0..7: row residue
    const int cb  = (threadIdx.x & 31) * 4;    // column base

    float m[4] = {-CUDART_INF_F, -CUDART_INF_F, -CUDART_INF_F, -CUDART_INF_F};
    float sum[4] = {0.f, 0.f, 0.f, 0.f};

    for (int r = lo + q; r < hi; r += 8) {
        float4 v = *reinterpret_cast<const float4*>(&logits[(size_t)r * CC + cb]);
        upd(m[0], sum[0], v.x);
        upd(m[1], sum[1], v.y);
        upd(m[2], sum[2], v.z);
        upd(m[3], sum[3], v.w);
    }
#pragma unroll
    for (int j = 0; j < 4; j++) {
        sm_m[q * 128 + cb + j] = m[j];
        sm_s[q * 128 + cb + j] = sum[j];
    }
    __syncthreads();

    // combine 8 partials per column (first 128 threads)
    if (threadIdx.x < 128) {
        const int c = threadIdx.x;
        float M = -CUDART_INF_F, S = 0.f;
#pragma unroll
        for (int qq = 0; qq < 8; qq++) {
            float mq = sm_m[qq * 128 + c], sq = sm_s[qq * 128 + c];
            if (sq > 0.f) {
                float nm = fmaxf(M, mq);
                S = S * __expf(M - nm) + sq * __expf(mq - nm);
                M = nm;
            }
        }
        sm_m[c] = M;                              // safe: qq=0 slot, all reads done? no —
        sm_s[c] = (S > 0.f) ? (1.f / S) : 0.f;    // guarded by syncthreads below before reuse
    }
    __syncthreads();

    float mm[4], ii[4];
#pragma unroll
    for (int j = 0; j < 4; j++) { mm[j] = sm_m[cb + j]; ii[j] = sm_s[cb + j]; }

    for (int r = lo + q; r < hi; r += 8) {
        float4 v = *reinterpret_cast<const float4*>(&logits[(size_t)r * CC + cb]);
        float4 o;
        o.x = __expf(v.x - mm[0]) * ii[0];
        o.y = __expf(v.y - mm[1]) * ii[1];
        o.z = __expf(v.z - mm[2]) * ii[2];
        o.w = __expf(v.w - mm[3]) * ii[3];
        *reinterpret_cast<float4*>(&probs[(size_t)r * CC + cb]) = o;
    }
}

// ===========================================================================
// Launch
// ===========================================================================
extern "C" void kernel_launch(void* const* d_in, const int* in_sizes, int n_in,
                              void* d_out, int out_size)
{
    const float* H  = nullptr;
    const int*   batch = nullptr;
    const float* W1 = nullptr;
    const float* b1 = nullptr;
    const float* W2 = nullptr;
    const float* b2 = nullptr;

    for (int i = 0; i < n_in; i++) {
        switch (in_sizes[i]) {
            case 128000000: H     = (const float*)d_in[i]; break;
            case 500000:    batch = (const int*)d_in[i];   break;
            case 65536:     W1    = (const float*)d_in[i]; break;
            case 256:       b1    = (const float*)d_in[i]; break;
            case 32768:     W2    = (const float*)d_in[i]; break;
            case 128:       b2    = (const float*)d_in[i]; break;
            default: break;
        }
    }

    float* out    = (float*)d_out;
    float* logits = out;
    float* probs  = out + (size_t)NN * CC;

    void *h16, *w1hi, *w1lo, *w2hi, *w2lo;
    cudaGetSymbolAddress(&h16, g_h16);
    cudaGetSymbolAddress(&w1hi, g_w1hi);
    cudaGetSymbolAddress(&w1lo, g_w1lo);
    cudaGetSymbolAddress(&w2hi, g_w2hi);
    cudaGetSymbolAddress(&w2lo, g_w2lo);

    cudaFuncSetAttribute(gemm_hmma<0, 1, 0>,
                         cudaFuncAttributeMaxDynamicSharedMemorySize, SMEM_BYTES);
    cudaFuncSetAttribute(gemm_hmma<1, 0, 1>,
                         cudaFuncAttributeMaxDynamicSharedMemorySize, SMEM_BYTES);

    convert_w<<<192, 256>>>(W1, W2);

    const int mblocks = (NN + BM - 1) / BM;    // 3907

    // Layer 1: h = relu(H @ W1 + b1), single product (W1 hi only), fp16 h out
    dim3 g1(mblocks, DD / BN);                 // 3907 x 2
    gemm_hmma<0, 1, 0><<<g1, 256, SMEM_BYTES>>>(
        H, nullptr, (const uint32_t*)w1hi, nullptr,
        b1, nullptr, (uint32_t*)h16, NN, DD, 1);

    // Layer 2: logits = h @ W2 + b2, 2-product (W2 split), fp32 out
    dim3 g2(mblocks, CC / BN);                 // 3907 x 1
    gemm_hmma<1, 0, 1><<<g2, 256, SMEM_BYTES>>>(
        nullptr, (const uint32_t*)h16, (const uint32_t*)w2hi, (const uint32_t*)w2lo,
        b2, logits, nullptr, NN, CC, 0);

    // Segment softmax -> probs
    seg_softmax<<<SSEG, 256>>>(logits, batch, probs);
}